// round 7
// baseline (speedup 1.0000x reference)
#include <cuda_runtime.h>
#include <cuda_bf16.h>

// ---------------------------------------------------------------------------
// OT (Sinkhorn) attention, B=8, N=1024, D=64, fp32.
// Scaling-form Sinkhorn, fused row pass, push-based DSMEM cluster reduce.
// bf16 S (16 MB, L2-resident). One cluster per batch (16 CTAs if allowed).
// ---------------------------------------------------------------------------

#define BATCH 8
#define NSEQ  1024
#define DIM   64
#define EPS_F 0.05f
#define MU_F  (1.0f/1024.0f + 1e-8f)

__device__ __nv_bfloat16 g_S[(size_t)BATCH * NSEQ * NSEQ];   // 16 MB
__device__ float g_Qn[BATCH * NSEQ * DIM];
__device__ float g_Kn[BATCH * NSEQ * DIM];
__device__ float g_a[BATCH * NSEQ];
__device__ float g_w[BATCH * NSEQ];

// ---------------- helpers ----------------
__device__ __forceinline__ float bflo(unsigned x) { return __uint_as_float(x << 16); }
__device__ __forceinline__ float bfhi(unsigned x) { return __uint_as_float(x & 0xFFFF0000u); }

__device__ __forceinline__ unsigned pk2(float a, float b) {
    __nv_bfloat162 t = __floats2bfloat162_rn(a, b);  // .x = a (low)
    return *reinterpret_cast<unsigned*>(&t);
}

__device__ __forceinline__ unsigned smem_u32(const void* p) {
    unsigned a;
    asm("{ .reg .u64 t; cvta.to.shared.u64 t, %1; cvt.u32.u64 %0, t; }" : "=r"(a) : "l"(p));
    return a;
}
__device__ __forceinline__ unsigned cluster_rank() {
    unsigned r; asm("mov.u32 %0, %%cluster_ctarank;" : "=r"(r)); return r;
}
__device__ __forceinline__ unsigned cluster_nctas() {
    unsigned r; asm("mov.u32 %0, %%cluster_nctaid.x;" : "=r"(r)); return r;
}
__device__ __forceinline__ unsigned mapa_u32(unsigned addr, unsigned rank) {
    unsigned r; asm("mapa.shared::cluster.u32 %0, %1, %2;" : "=r"(r) : "r"(addr), "r"(rank));
    return r;
}
__device__ __forceinline__ void st_dsmem_f32(unsigned addr, float v) {
    asm volatile("st.shared::cluster.f32 [%0], %1;" :: "r"(addr), "f"(v));
}
#define CLUSTER_SYNC() do { \
    asm volatile("barrier.cluster.arrive.aligned;" ::: "memory"); \
    asm volatile("barrier.cluster.wait.aligned;"   ::: "memory"); \
} while (0)

// ---------------- kernel 1: L2-normalize rows of q,k ----------------
__global__ void __launch_bounds__(256) norm_kernel(const float* __restrict__ q,
                                                   const float* __restrict__ k) {
    int gw   = (blockIdx.x * 256 + threadIdx.x) >> 5;
    int lane = threadIdx.x & 31;
    const float* src;
    float* dst;
    if (gw < BATCH * NSEQ) { src = q + (size_t)gw * DIM;                dst = g_Qn + (size_t)gw * DIM; }
    else                   { src = k + (size_t)(gw - BATCH*NSEQ) * DIM; dst = g_Kn + (size_t)(gw - BATCH*NSEQ) * DIM; }
    float2 v = reinterpret_cast<const float2*>(src)[lane];
    float s = v.x * v.x + v.y * v.y;
    #pragma unroll
    for (int o = 16; o > 0; o >>= 1) s += __shfl_xor_sync(~0u, s, o);
    float n   = sqrtf(s);
    float inv = 1.0f / fmaxf(n, 1e-12f);
    reinterpret_cast<float2*>(dst)[lane] = make_float2(v.x * inv, v.y * inv);
}

// ---------------- kernel 2: S = exp((QK^T - 1)/eps), bf16 ----------------
__global__ void __launch_bounds__(256) gemmS_kernel() {
    int b  = blockIdx.y;
    int i0 = blockIdx.x * 32;
    __shared__ __align__(16) float Qs[32][DIM];
    __shared__ __align__(16) float Ks[128][DIM];

    const float* Qp = g_Qn + (size_t)(b * NSEQ + i0) * DIM;
    for (int t = threadIdx.x; t < 32 * DIM / 4; t += 256)
        reinterpret_cast<float4*>(&Qs[0][0])[t] = reinterpret_cast<const float4*>(Qp)[t];

    int ti = threadIdx.x >> 5;
    int tj = threadIdx.x & 31;

    for (int jt = 0; jt < NSEQ; jt += 128) {
        __syncthreads();
        const float* Kp = g_Kn + (size_t)(b * NSEQ + jt) * DIM;
        for (int t = threadIdx.x; t < 128 * DIM / 4; t += 256)
            reinterpret_cast<float4*>(&Ks[0][0])[t] = reinterpret_cast<const float4*>(Kp)[t];
        __syncthreads();

        float acc[4][4];
        #pragma unroll
        for (int r = 0; r < 4; ++r)
            #pragma unroll
            for (int c = 0; c < 4; ++c) acc[r][c] = 0.f;

        #pragma unroll
        for (int d = 0; d < DIM; d += 4) {
            float4 qv[4], kv[4];
            #pragma unroll
            for (int r = 0; r < 4; ++r) qv[r] = *reinterpret_cast<const float4*>(&Qs[4*ti + r][d]);
            #pragma unroll
            for (int c = 0; c < 4; ++c) kv[c] = *reinterpret_cast<const float4*>(&Ks[4*tj + c][d]);
            #pragma unroll
            for (int r = 0; r < 4; ++r)
                #pragma unroll
                for (int c = 0; c < 4; ++c) {
                    acc[r][c] = fmaf(qv[r].x, kv[c].x, acc[r][c]);
                    acc[r][c] = fmaf(qv[r].y, kv[c].y, acc[r][c]);
                    acc[r][c] = fmaf(qv[r].z, kv[c].z, acc[r][c]);
                    acc[r][c] = fmaf(qv[r].w, kv[c].w, acc[r][c]);
                }
        }

        #pragma unroll
        for (int r = 0; r < 4; ++r) {
            size_t rowi = (size_t)(b * NSEQ + i0 + 4*ti + r);
            float e0 = __expf(20.0f * (acc[r][0] - 1.0f));
            float e1 = __expf(20.0f * (acc[r][1] - 1.0f));
            float e2 = __expf(20.0f * (acc[r][2] - 1.0f));
            float e3 = __expf(20.0f * (acc[r][3] - 1.0f));
            uint2 p = make_uint2(pk2(e0, e1), pk2(e2, e3));
            *reinterpret_cast<uint2*>(g_S + (rowi << 10) + jt + 4*tj) = p;
        }
    }
}

// ---------------- kernel 3: fused Sinkhorn loop ----------------
// grid = BATCH * csz CTAs (csz-CTA cluster per batch), 512 threads.
// dynamic smem: sw[1024] | sstage[1024] | wbuf[16][1024]
__global__ void __launch_bounds__(512) sink_kernel() {
    extern __shared__ float dynS[];
    float* sw     = dynS;           // full w for this batch (4 KB)
    float* sstage = dynS + 1024;    // [csz][colsPerCta] push-staging (4 KB)
    float* wbuf   = dynS + 2048;    // [16][1024] warp partials (64 KB)

    __shared__ float sa[128];
    __shared__ float swErr[16];
    __shared__ float errstage[16];
    __shared__ int   sBreak;

    unsigned csz  = cluster_nctas();          // 8 or 16
    unsigned rank = cluster_rank();
    int b           = blockIdx.x / (int)csz;
    int rowsPerCta  = NSEQ / (int)csz;        // 128 or 64
    int rowsPerWarp = rowsPerCta >> 4;        // 8 or 4 (even)
    int colsPerCta  = NSEQ / (int)csz;
    int colsShift   = 31 - __clz(colsPerCta); // log2
    int tid  = threadIdx.x;
    int wid  = tid >> 5;
    int lane = tid & 31;

    for (int t = tid; t < NSEQ; t += 512) sw[t] = 1.0f;
    if (tid < rowsPerCta) sa[tid] = 1.0f;
    if (tid == 0) sBreak = 0;
    __syncthreads();

    const __nv_bfloat16* Sbase = g_S + ((size_t)(b * NSEQ + (int)rank * rowsPerCta) << 10);

    unsigned sstage_u32 = smem_u32(sstage);
    unsigned sw_u32     = smem_u32(sw);
    unsigned errst_u32  = smem_u32(errstage);

    #pragma unroll 1
    for (int iter = 0; iter < 100; ++iter) {
        // preload w into registers: lane covers cols {c*256 + lane*8 + e}
        float wr[4][8];
        #pragma unroll
        for (int c = 0; c < 4; ++c) {
            float4 w0 = *reinterpret_cast<const float4*>(&sw[c*256 + lane*8]);
            float4 w1 = *reinterpret_cast<const float4*>(&sw[c*256 + lane*8 + 4]);
            wr[c][0] = w0.x; wr[c][1] = w0.y; wr[c][2] = w0.z; wr[c][3] = w0.w;
            wr[c][4] = w1.x; wr[c][5] = w1.y; wr[c][6] = w1.z; wr[c][7] = w1.w;
        }

        float cc[4][8];
        #pragma unroll
        for (int c = 0; c < 4; ++c)
            #pragma unroll
            for (int e = 0; e < 8; ++e) cc[c][e] = 0.f;

        float errAcc = 0.f;
        int row0 = wid * rowsPerWarp;

        // process one resident row: dot -> a_new -> rank-1
        auto process = [&](const uint4 (&v)[4], int row) {
            float a0 = 0.f, a1 = 0.f, a2 = 0.f, a3 = 0.f;
            #pragma unroll
            for (int c = 0; c < 4; ++c) {
                a0 = fmaf(bflo(v[c].x), wr[c][0], a0); a1 = fmaf(bfhi(v[c].x), wr[c][1], a1);
                a2 = fmaf(bflo(v[c].y), wr[c][2], a2); a3 = fmaf(bfhi(v[c].y), wr[c][3], a3);
                a0 = fmaf(bflo(v[c].z), wr[c][4], a0); a1 = fmaf(bfhi(v[c].z), wr[c][5], a1);
                a2 = fmaf(bflo(v[c].w), wr[c][6], a2); a3 = fmaf(bfhi(v[c].w), wr[c][7], a3);
            }
            float acc = (a0 + a1) + (a2 + a3);
            #pragma unroll
            for (int o = 16; o > 0; o >>= 1) acc += __shfl_xor_sync(~0u, acc, o);
            float anew = MU_F / acc;
            if (lane == 0) {
                float aold = sa[row];
                sa[row] = anew;
                errAcc += fabsf(EPS_F * (__logf(anew) - __logf(aold)));
            }
            #pragma unroll
            for (int c = 0; c < 4; ++c) {
                cc[c][0] = fmaf(bflo(v[c].x), anew, cc[c][0]);
                cc[c][1] = fmaf(bfhi(v[c].x), anew, cc[c][1]);
                cc[c][2] = fmaf(bflo(v[c].y), anew, cc[c][2]);
                cc[c][3] = fmaf(bfhi(v[c].y), anew, cc[c][3]);
                cc[c][4] = fmaf(bflo(v[c].z), anew, cc[c][4]);
                cc[c][5] = fmaf(bfhi(v[c].z), anew, cc[c][5]);
                cc[c][6] = fmaf(bflo(v[c].w), anew, cc[c][6]);
                cc[c][7] = fmaf(bfhi(v[c].w), anew, cc[c][7]);
            }
        };

        // double-buffered row streaming
        uint4 va[4], vb[4];
        {
            const uint4* p0 = reinterpret_cast<const uint4*>(Sbase + ((size_t)row0 << 10));
            #pragma unroll
            for (int c = 0; c < 4; ++c) va[c] = p0[c*32 + lane];
        }
        #pragma unroll 1
        for (int r8 = 0; r8 < rowsPerWarp; r8 += 2) {
            const uint4* p1 = reinterpret_cast<const uint4*>(Sbase + ((size_t)(row0 + r8 + 1) << 10));
            #pragma unroll
            for (int c = 0; c < 4; ++c) vb[c] = p1[c*32 + lane];
            process(va, row0 + r8);
            if (r8 + 2 < rowsPerWarp) {
                const uint4* p2 = reinterpret_cast<const uint4*>(Sbase + ((size_t)(row0 + r8 + 2) << 10));
                #pragma unroll
                for (int c = 0; c < 4; ++c) va[c] = p2[c*32 + lane];
            }
            process(vb, row0 + r8 + 1);
        }
        if (lane == 0) swErr[wid] = errAcc;

        // ---- single-stage warp reduce: store warp partials to wbuf
        {
            float* dstw = &wbuf[wid * 1024];
            #pragma unroll
            for (int c = 0; c < 4; ++c) {
                float* dst = &dstw[c*256 + lane*8];
                *reinterpret_cast<float4*>(dst)     = make_float4(cc[c][0], cc[c][1], cc[c][2], cc[c][3]);
                *reinterpret_cast<float4*>(dst + 4) = make_float4(cc[c][4], cc[c][5], cc[c][6], cc[c][7]);
            }
        }
        __syncthreads();

        // ---- each thread reduces 2 columns over 16 warps, pushes to owner rank
        {
            int col0 = tid * 2;
            float c0 = 0.f, c1 = 0.f;
            #pragma unroll
            for (int wu = 0; wu < 16; ++wu) {
                float2 x = *reinterpret_cast<const float2*>(&wbuf[wu*1024 + col0]);
                c0 += x.x; c1 += x.y;
            }
            unsigned dr   = (unsigned)(col0 >> colsShift);
            int      lcol = col0 & (colsPerCta - 1);
            unsigned raddr = mapa_u32(sstage_u32 + 4u*((int)rank*colsPerCta + lcol), dr);
            st_dsmem_f32(raddr,      c0);
            st_dsmem_f32(raddr + 4u, c1);
        }
        // err push (one thread): sum warp errors, broadcast to all ranks' errstage[myrank]
        if (tid == 256) {
            float e = 0.f;
            #pragma unroll
            for (int t2 = 0; t2 < 16; ++t2) e += swErr[t2];
            for (unsigned r2 = 0; r2 < csz; ++r2)
                st_dsmem_f32(mapa_u32(errst_u32 + 4u*rank, r2), e);
        }
        CLUSTER_SYNC();   // all pushes visible

        // ---- owner: reduce csz local partials, push w to all ranks
        if (tid < colsPerCta) {
            float cs = 0.f;
            for (unsigned r2 = 0; r2 < csz; ++r2)
                cs += sstage[(int)r2 * colsPerCta + tid];
            float wnew = MU_F / cs;
            int col = (int)rank * colsPerCta + tid;
            for (unsigned r2 = 0; r2 < csz; ++r2)
                st_dsmem_f32(mapa_u32(sw_u32 + 4u*col, r2), wnew);
        } else if (tid == colsPerCta) {
            float e = 0.f;
            for (unsigned r2 = 0; r2 < csz; ++r2) e += errstage[r2];
            sBreak = (e < 1.28e-4f) ? 1 : 0;   // stricter than ref's global break
        }
        CLUSTER_SYNC();   // w visible everywhere; sBreak visible CTA-wide
        if (sBreak) break;
    }

    if (tid < rowsPerCta)
        g_a[b * NSEQ + (int)rank * rowsPerCta + tid] = sa[tid];
    if (tid < colsPerCta)
        g_w[b * NSEQ + (int)rank * colsPerCta + tid] = sw[(int)rank * colsPerCta + tid];
}

// ---------------- kernel 4: out = a (.) (S (w (.) V)) + V ----------------
// grid (16, 8): 64-row blocks x batch, 256 threads.
// Thread = (rg, dg): rows {rg+16*rr}, d = 4*dg..+3 -> 4x4 register tile.
// S staged untransposed as bf16-pairs (u32), row stride 65 (odd -> conflict-free).
__global__ void __launch_bounds__(256) out_kernel(const float* __restrict__ V,
                                                  float* __restrict__ out) {
    int b  = blockIdx.y;
    int i0 = blockIdx.x * 64;
    extern __shared__ float dynO[];
    float*    Yt   = dynO;                              // [128][64] fp32, 32 KB
    unsigned* Srow = (unsigned*)(dynO + 128*64);        // [64][65] u32 pairs, 16.6 KB
    __shared__ float wt[128];

    int tid = threadIdx.x;
    int rg  = tid & 15;     // row group: rows rg + 16*rr
    int dg  = tid >> 4;     // d = 4*dg .. +3

    float acc[4][4];
    #pragma unroll
    for (int r = 0; r < 4; ++r)
        #pragma unroll
        for (int c = 0; c < 4; ++c) acc[r][c] = 0.f;

    const float* Vb = V + (size_t)b * NSEQ * DIM;

    for (int jt = 0; jt < NSEQ; jt += 128) {
        __syncthreads();
        if (tid < 128) wt[tid] = g_w[b * NSEQ + jt + tid];
        __syncthreads();
        // Yt[j][d] = w[jt+j] * V[b][jt+j][d]
        for (int t = tid; t < 2048; t += 256) {
            int j = t >> 4, dq = t & 15;
            float4 v4 = reinterpret_cast<const float4*>(Vb + (size_t)(jt + j) * DIM)[dq];
            float wv = wt[j];
            *reinterpret_cast<float4*>(&Yt[j*64 + dq*4]) =
                make_float4(v4.x*wv, v4.y*wv, v4.z*wv, v4.w*wv);
        }
        // Srow[r][jh] = S[b][i0+r][jt + 2jh .. +1] as u32 pair
        const __nv_bfloat16* Sb2 = g_S + ((size_t)(b * NSEQ + i0) << 10) + jt;
        #pragma unroll
        for (int k = 0; k < 4; ++k) {
            int idx = tid + 256*k;          // 0..1023
            int r = idx >> 4, q4 = idx & 15;
            uint4 v = *reinterpret_cast<const uint4*>(Sb2 + ((size_t)r << 10) + q4*8);
            unsigned* dst = &Srow[r*65 + q4*4];
            dst[0] = v.x; dst[1] = v.y; dst[2] = v.z; dst[3] = v.w;
        }
        __syncthreads();

        #pragma unroll 4
        for (int jh = 0; jh < 64; ++jh) {
            unsigned sp0 = Srow[(rg     )*65 + jh];
            unsigned sp1 = Srow[(rg + 16)*65 + jh];
            unsigned sp2 = Srow[(rg + 32)*65 + jh];
            unsigned sp3 = Srow[(rg + 48)*65 + jh];
            float4 y0 = *reinterpret_cast<const float4*>(&Yt[(2*jh  )*64 + dg*4]);
            float4 y1 = *reinterpret_cast<const float4*>(&Yt[(2*jh+1)*64 + dg*4]);
            float s0, s1;
            s0 = bflo(sp0); s1 = bfhi(sp0);
            acc[0][0] = fmaf(s1, y1.x, fmaf(s0, y0.x, acc[0][0]));
            acc[0][1] = fmaf(s1, y1.y, fmaf(s0, y0.y, acc[0][1]));
            acc[0][2] = fmaf(s1, y1.z, fmaf(s0, y0.z, acc[0][2]));
            acc[0][3] = fmaf(s1, y1.w, fmaf(s0, y0.w, acc[0][3]));
            s0 = bflo(sp1); s1 = bfhi(sp1);
            acc[1][0] = fmaf(s1, y1.x, fmaf(s0, y0.x, acc[1][0]));
            acc[1][1] = fmaf(s1, y1.y, fmaf(s0, y0.y, acc[1][1]));
            acc[1][2] = fmaf(s1, y1.z, fmaf(s0, y0.z, acc[1][2]));
            acc[1][3] = fmaf(s1, y1.w, fmaf(s0, y0.w, acc[1][3]));
            s0 = bflo(sp2); s1 = bfhi(sp2);
            acc[2][0] = fmaf(s1, y1.x, fmaf(s0, y0.x, acc[2][0]));
            acc[2][1] = fmaf(s1, y1.y, fmaf(s0, y0.y, acc[2][1]));
            acc[2][2] = fmaf(s1, y1.z, fmaf(s0, y0.z, acc[2][2]));
            acc[2][3] = fmaf(s1, y1.w, fmaf(s0, y0.w, acc[2][3]));
            s0 = bflo(sp3); s1 = bfhi(sp3);
            acc[3][0] = fmaf(s1, y1.x, fmaf(s0, y0.x, acc[3][0]));
            acc[3][1] = fmaf(s1, y1.y, fmaf(s0, y0.y, acc[3][1]));
            acc[3][2] = fmaf(s1, y1.z, fmaf(s0, y0.z, acc[3][2]));
            acc[3][3] = fmaf(s1, y1.w, fmaf(s0, y0.w, acc[3][3]));
        }
    }

    #pragma unroll
    for (int rr = 0; rr < 4; ++rr) {
        int row = i0 + rg + 16*rr;
        float a = g_a[b * NSEQ + row];
        float4 v4 = *reinterpret_cast<const float4*>(&Vb[(size_t)row * DIM + dg*4]);
        float4 o;
        o.x = fmaf(acc[rr][0], a, v4.x);
        o.y = fmaf(acc[rr][1], a, v4.y);
        o.z = fmaf(acc[rr][2], a, v4.z);
        o.w = fmaf(acc[rr][3], a, v4.w);
        *reinterpret_cast<float4*>(&out[((size_t)b * NSEQ + row) * DIM + dg*4]) = o;
    }
}

// ---------------- launcher ----------------
extern "C" void kernel_launch(void* const* d_in, const int* in_sizes, int n_in,
                              void* d_out, int out_size) {
    const float* q = (const float*)d_in[0];
    const float* k = (const float*)d_in[1];
    const float* V = (const float*)d_in[2];
    float* out = (float*)d_out;
    (void)in_sizes; (void)n_in; (void)out_size;

    const int sinkSmem = (1024 + 1024 + 16*1024) * (int)sizeof(float);   // 73728
    const int outSmem  = (128*64 + 64*65) * (int)sizeof(float);          // 49408

    cudaFuncSetAttribute(sink_kernel, cudaFuncAttributeMaxDynamicSharedMemorySize, sinkSmem);
    cudaFuncSetAttribute(out_kernel,  cudaFuncAttributeMaxDynamicSharedMemorySize, outSmem);
    cudaFuncSetAttribute(sink_kernel, cudaFuncAttributeNonPortableClusterSizeAllowed, 1);

    int csz = 8;
    {
        int maxC = 0;
        cudaLaunchConfig_t qcfg = {};
        qcfg.gridDim  = dim3(128);
        qcfg.blockDim = dim3(512);
        qcfg.dynamicSmemBytes = sinkSmem;
        if (cudaOccupancyMaxPotentialClusterSize(&maxC, sink_kernel, &qcfg) == cudaSuccess) {
            if (maxC >= 16) csz = 16;
        }
    }

    norm_kernel<<<2048, 256>>>(q, k);
    gemmS_kernel<<<dim3(32, 8), 256>>>();

    {
        cudaLaunchAttribute at;
        at.id = cudaLaunchAttributeClusterDimension;
        at.val.clusterDim.x = (unsigned)csz;
        at.val.clusterDim.y = 1;
        at.val.clusterDim.z = 1;
        cudaLaunchConfig_t cfg = {};
        cfg.gridDim  = dim3((unsigned)(BATCH * csz));
        cfg.blockDim = dim3(512);
        cfg.dynamicSmemBytes = sinkSmem;
        cfg.stream = 0;
        cfg.attrs = &at;
        cfg.numAttrs = 1;
        cudaLaunchKernelEx(&cfg, sink_kernel);
    }

    out_kernel<<<dim3(16, 8), 256, outSmem>>>(V, out);
}

// round 9
// speedup vs baseline: 1.4684x; 1.4684x over previous
#include <cuda_runtime.h>
#include <cuda_bf16.h>

// ---------------------------------------------------------------------------
// OT (Sinkhorn) attention, B=8, N=1024, D=64, fp32.
// Scaling-form Sinkhorn with FUSED passes (R5 proven version): stream each
// row of S once per iteration; dot with w -> a_new -> rank-1 update.
// bf16 S (16 MB, L2-resident). One cluster per batch (16 CTAs if allowed).
// out_kernel: 512-thread CTAs, occupancy-optimized.
// ---------------------------------------------------------------------------

#define BATCH 8
#define NSEQ  1024
#define DIM   64
#define EPS_F 0.05f
#define MU_F  (1.0f/1024.0f + 1e-8f)

__device__ __nv_bfloat16 g_S[(size_t)BATCH * NSEQ * NSEQ];   // 16 MB
__device__ float g_Qn[BATCH * NSEQ * DIM];
__device__ float g_Kn[BATCH * NSEQ * DIM];
__device__ float g_a[BATCH * NSEQ];
__device__ float g_w[BATCH * NSEQ];

// ---------------- helpers ----------------
__device__ __forceinline__ float bflo(unsigned x) { return __uint_as_float(x << 16); }
__device__ __forceinline__ float bfhi(unsigned x) { return __uint_as_float(x & 0xFFFF0000u); }

__device__ __forceinline__ unsigned pk2(float a, float b) {
    __nv_bfloat162 t = __floats2bfloat162_rn(a, b);  // .x = a (low)
    return *reinterpret_cast<unsigned*>(&t);
}

__device__ __forceinline__ unsigned smem_u32(const void* p) {
    unsigned a;
    asm("{ .reg .u64 t; cvta.to.shared.u64 t, %1; cvt.u32.u64 %0, t; }" : "=r"(a) : "l"(p));
    return a;
}
__device__ __forceinline__ unsigned cluster_rank() {
    unsigned r; asm("mov.u32 %0, %%cluster_ctarank;" : "=r"(r)); return r;
}
__device__ __forceinline__ unsigned cluster_nctas() {
    unsigned r; asm("mov.u32 %0, %%cluster_nctaid.x;" : "=r"(r)); return r;
}
__device__ __forceinline__ unsigned mapa_u32(unsigned addr, unsigned rank) {
    unsigned r; asm("mapa.shared::cluster.u32 %0, %1, %2;" : "=r"(r) : "r"(addr), "r"(rank));
    return r;
}
__device__ __forceinline__ float ld_dsmem_f32(unsigned addr) {
    float v; asm volatile("ld.shared::cluster.f32 %0, [%1];" : "=f"(v) : "r"(addr)); return v;
}
__device__ __forceinline__ void st_dsmem_f32(unsigned addr, float v) {
    asm volatile("st.shared::cluster.f32 [%0], %1;" :: "r"(addr), "f"(v));
}
#define CLUSTER_SYNC() do { \
    asm volatile("barrier.cluster.arrive.aligned;" ::: "memory"); \
    asm volatile("barrier.cluster.wait.aligned;"   ::: "memory"); \
} while (0)

// ---------------- kernel 1: L2-normalize rows of q,k ----------------
__global__ void __launch_bounds__(256) norm_kernel(const float* __restrict__ q,
                                                   const float* __restrict__ k) {
    int gw   = (blockIdx.x * 256 + threadIdx.x) >> 5;
    int lane = threadIdx.x & 31;
    const float* src;
    float* dst;
    if (gw < BATCH * NSEQ) { src = q + (size_t)gw * DIM;                dst = g_Qn + (size_t)gw * DIM; }
    else                   { src = k + (size_t)(gw - BATCH*NSEQ) * DIM; dst = g_Kn + (size_t)(gw - BATCH*NSEQ) * DIM; }
    float2 v = reinterpret_cast<const float2*>(src)[lane];
    float s = v.x * v.x + v.y * v.y;
    #pragma unroll
    for (int o = 16; o > 0; o >>= 1) s += __shfl_xor_sync(~0u, s, o);
    float n   = sqrtf(s);
    float inv = 1.0f / fmaxf(n, 1e-12f);
    reinterpret_cast<float2*>(dst)[lane] = make_float2(v.x * inv, v.y * inv);
}

// ---------------- kernel 2: S = exp((QK^T - 1)/eps), bf16 ----------------
__global__ void __launch_bounds__(256) gemmS_kernel() {
    int b  = blockIdx.y;
    int i0 = blockIdx.x * 32;
    __shared__ __align__(16) float Qs[32][DIM];
    __shared__ __align__(16) float Ks[128][DIM];

    const float* Qp = g_Qn + (size_t)(b * NSEQ + i0) * DIM;
    for (int t = threadIdx.x; t < 32 * DIM / 4; t += 256)
        reinterpret_cast<float4*>(&Qs[0][0])[t] = reinterpret_cast<const float4*>(Qp)[t];

    int ti = threadIdx.x >> 5;
    int tj = threadIdx.x & 31;

    for (int jt = 0; jt < NSEQ; jt += 128) {
        __syncthreads();
        const float* Kp = g_Kn + (size_t)(b * NSEQ + jt) * DIM;
        for (int t = threadIdx.x; t < 128 * DIM / 4; t += 256)
            reinterpret_cast<float4*>(&Ks[0][0])[t] = reinterpret_cast<const float4*>(Kp)[t];
        __syncthreads();

        float acc[4][4];
        #pragma unroll
        for (int r = 0; r < 4; ++r)
            #pragma unroll
            for (int c = 0; c < 4; ++c) acc[r][c] = 0.f;

        #pragma unroll
        for (int d = 0; d < DIM; d += 4) {
            float4 qv[4], kv[4];
            #pragma unroll
            for (int r = 0; r < 4; ++r) qv[r] = *reinterpret_cast<const float4*>(&Qs[4*ti + r][d]);
            #pragma unroll
            for (int c = 0; c < 4; ++c) kv[c] = *reinterpret_cast<const float4*>(&Ks[4*tj + c][d]);
            #pragma unroll
            for (int r = 0; r < 4; ++r)
                #pragma unroll
                for (int c = 0; c < 4; ++c) {
                    acc[r][c] = fmaf(qv[r].x, kv[c].x, acc[r][c]);
                    acc[r][c] = fmaf(qv[r].y, kv[c].y, acc[r][c]);
                    acc[r][c] = fmaf(qv[r].z, kv[c].z, acc[r][c]);
                    acc[r][c] = fmaf(qv[r].w, kv[c].w, acc[r][c]);
                }
        }

        #pragma unroll
        for (int r = 0; r < 4; ++r) {
            size_t rowi = (size_t)(b * NSEQ + i0 + 4*ti + r);
            float e0 = __expf(20.0f * (acc[r][0] - 1.0f));
            float e1 = __expf(20.0f * (acc[r][1] - 1.0f));
            float e2 = __expf(20.0f * (acc[r][2] - 1.0f));
            float e3 = __expf(20.0f * (acc[r][3] - 1.0f));
            uint2 p = make_uint2(pk2(e0, e1), pk2(e2, e3));
            *reinterpret_cast<uint2*>(g_S + (rowi << 10) + jt + 4*tj) = p;
        }
    }
}

// ---------------- kernel 3: fused Sinkhorn loop (R5 proven version) ----------------
// grid = BATCH * csz CTAs, one csz-CTA cluster per batch, 512 threads.
__global__ void __launch_bounds__(512) sink_kernel() {
    __shared__ __align__(16) float sw[NSEQ];        // 4 KB  full w (batch)
    __shared__ __align__(16) float sa[128];         // my a slice
    __shared__ __align__(16) float spc[NSEQ];       // 4 KB  CTA-partial c
    __shared__ __align__(16) float redbuf[8][NSEQ]; // 32 KB warp-tree buffer
    __shared__ float swErr[16];
    __shared__ float sErrTot;
    __shared__ int   sBreak;

    unsigned csz  = cluster_nctas();          // 8 or 16
    unsigned rank = cluster_rank();
    int b           = blockIdx.x / (int)csz;
    int rowsPerCta  = NSEQ / (int)csz;        // 128 or 64
    int rowsPerWarp = rowsPerCta >> 4;        // 8 or 4
    int colsPerCta  = NSEQ / (int)csz;
    int tid  = threadIdx.x;
    int wid  = tid >> 5;
    int lane = tid & 31;

    for (int t = tid; t < NSEQ; t += 512) sw[t] = 1.0f;
    if (tid < rowsPerCta) sa[tid] = 1.0f;
    if (tid == 0) sBreak = 0;
    __syncthreads();

    const __nv_bfloat16* Sbase = g_S + ((size_t)(b * NSEQ + (int)rank * rowsPerCta) << 10);

    unsigned spc_u32 = smem_u32(spc);
    unsigned sw_u32  = smem_u32(sw);
    unsigned err_u32 = smem_u32(&sErrTot);

    #pragma unroll 1
    for (int iter = 0; iter < 100; ++iter) {
        // preload w: lane covers cols {c*256 + lane*8 + e}
        float wr[4][8];
        #pragma unroll
        for (int c = 0; c < 4; ++c) {
            float4 w0 = *reinterpret_cast<const float4*>(&sw[c*256 + lane*8]);
            float4 w1 = *reinterpret_cast<const float4*>(&sw[c*256 + lane*8 + 4]);
            wr[c][0] = w0.x; wr[c][1] = w0.y; wr[c][2] = w0.z; wr[c][3] = w0.w;
            wr[c][4] = w1.x; wr[c][5] = w1.y; wr[c][6] = w1.z; wr[c][7] = w1.w;
        }

        float cc[4][8];
        #pragma unroll
        for (int c = 0; c < 4; ++c)
            #pragma unroll
            for (int e = 0; e < 8; ++e) cc[c][e] = 0.f;

        float errAcc = 0.f;

        // ---- fused pass: per row, dot -> a_new -> rank-1
        #pragma unroll 1
        for (int r8 = 0; r8 < rowsPerWarp; ++r8) {
            int row = wid * rowsPerWarp + r8;
            const uint4* p = reinterpret_cast<const uint4*>(Sbase + ((size_t)row << 10));
            uint4 v[4];
            #pragma unroll
            for (int c = 0; c < 4; ++c) v[c] = p[c*32 + lane];

            float a0 = 0.f, a1 = 0.f, a2 = 0.f, a3 = 0.f;
            #pragma unroll
            for (int c = 0; c < 4; ++c) {
                a0 = fmaf(bflo(v[c].x), wr[c][0], a0); a1 = fmaf(bfhi(v[c].x), wr[c][1], a1);
                a2 = fmaf(bflo(v[c].y), wr[c][2], a2); a3 = fmaf(bfhi(v[c].y), wr[c][3], a3);
                a0 = fmaf(bflo(v[c].z), wr[c][4], a0); a1 = fmaf(bfhi(v[c].z), wr[c][5], a1);
                a2 = fmaf(bflo(v[c].w), wr[c][6], a2); a3 = fmaf(bfhi(v[c].w), wr[c][7], a3);
            }
            float acc = (a0 + a1) + (a2 + a3);
            #pragma unroll
            for (int o = 16; o > 0; o >>= 1) acc += __shfl_xor_sync(~0u, acc, o);

            float anew = MU_F / acc;   // all lanes
            if (lane == 0) {
                float aold = sa[row];
                sa[row] = anew;
                errAcc += fabsf(EPS_F * (__logf(anew) - __logf(aold)));
            }
            // rank-1: cc_j += s_ij * a_new
            #pragma unroll
            for (int c = 0; c < 4; ++c) {
                cc[c][0] = fmaf(bflo(v[c].x), anew, cc[c][0]);
                cc[c][1] = fmaf(bfhi(v[c].x), anew, cc[c][1]);
                cc[c][2] = fmaf(bflo(v[c].y), anew, cc[c][2]);
                cc[c][3] = fmaf(bfhi(v[c].y), anew, cc[c][3]);
                cc[c][4] = fmaf(bflo(v[c].z), anew, cc[c][4]);
                cc[c][5] = fmaf(bfhi(v[c].z), anew, cc[c][5]);
                cc[c][6] = fmaf(bflo(v[c].w), anew, cc[c][6]);
                cc[c][7] = fmaf(bfhi(v[c].w), anew, cc[c][7]);
            }
        }
        if (lane == 0) swErr[wid] = errAcc;

        // ---- warp tree: 16 -> 1 column-accumulator reduction
        #pragma unroll
        for (int h = 8; h >= 1; h >>= 1) {
            if (wid >= h && wid < 2*h) {
                #pragma unroll
                for (int c = 0; c < 4; ++c) {
                    float* dst = &redbuf[wid - h][c*256 + lane*8];
                    *reinterpret_cast<float4*>(dst)     = make_float4(cc[c][0], cc[c][1], cc[c][2], cc[c][3]);
                    *reinterpret_cast<float4*>(dst + 4) = make_float4(cc[c][4], cc[c][5], cc[c][6], cc[c][7]);
                }
            }
            __syncthreads();
            if (wid < h) {
                #pragma unroll
                for (int c = 0; c < 4; ++c) {
                    const float* src = &redbuf[wid][c*256 + lane*8];
                    float4 s0 = *reinterpret_cast<const float4*>(src);
                    float4 s1 = *reinterpret_cast<const float4*>(src + 4);
                    cc[c][0] += s0.x; cc[c][1] += s0.y; cc[c][2] += s0.z; cc[c][3] += s0.w;
                    cc[c][4] += s1.x; cc[c][5] += s1.y; cc[c][6] += s1.z; cc[c][7] += s1.w;
                }
            }
            __syncthreads();
        }
        if (wid == 0) {
            #pragma unroll
            for (int c = 0; c < 4; ++c) {
                float* dst = &spc[c*256 + lane*8];
                *reinterpret_cast<float4*>(dst)     = make_float4(cc[c][0], cc[c][1], cc[c][2], cc[c][3]);
                *reinterpret_cast<float4*>(dst + 4) = make_float4(cc[c][4], cc[c][5], cc[c][6], cc[c][7]);
            }
        }
        if (tid == 0) {
            float e = 0.f;
            #pragma unroll
            for (int t2 = 0; t2 < 16; ++t2) e += swErr[t2];
            sErrTot = e;
        }
        __syncthreads();
        CLUSTER_SYNC();   // spc / sErrTot visible cluster-wide

        // ---- cross-CTA column reduce + w broadcast (rank owns colsPerCta cols)
        if (tid < colsPerCta) {
            int col = (int)rank * colsPerCta + tid;
            float cs = 0.f;
            for (unsigned r2 = 0; r2 < csz; ++r2)
                cs += ld_dsmem_f32(mapa_u32(spc_u32 + 4u*col, r2));
            float wnew = MU_F / cs;
            for (unsigned r2 = 0; r2 < csz; ++r2)
                st_dsmem_f32(mapa_u32(sw_u32 + 4u*col, r2), wnew);
        } else if (tid == colsPerCta) {
            float e = 0.f;
            for (unsigned r2 = 0; r2 < csz; ++r2)
                e += ld_dsmem_f32(mapa_u32(err_u32, r2));
            sBreak = (e < 1.28e-4f) ? 1 : 0;   // stricter than ref's global break
        }
        CLUSTER_SYNC();
        if (sBreak) break;
    }

    if (tid < rowsPerCta)
        g_a[b * NSEQ + (int)rank * rowsPerCta + tid] = sa[tid];
    if (tid < colsPerCta)
        g_w[b * NSEQ + (int)rank * colsPerCta + tid] = sw[(int)rank * colsPerCta + tid];
}

// ---------------- kernel 4: out = a (.) (S (w (.) V)) + V ----------------
// grid (32, 8): 32-row blocks x batch, 512 threads (16 warps).
// Thread = (lane=row-in-block, wid=d-group of 4). S^T staged row-major fp32
// Ssm[r][j], row stride 132 -> vectorized LDS.128 over 4 j's, conflict-free.
// 2 CTAs/SM -> ~50% occupancy (vs 12-21% before).
__global__ void __launch_bounds__(512) out_kernel(const float* __restrict__ V,
                                                  float* __restrict__ out) {
    int b  = blockIdx.y;
    int i0 = blockIdx.x * 32;
    extern __shared__ float dynO[];
    float* Yt  = dynO;              // [128][64] fp32, 32 KB
    float* Ssm = dynO + 128*64;     // [32][132] fp32, 16.5 KB
    __shared__ float wt[128];

    int tid  = threadIdx.x;
    int wid  = tid >> 5;    // d-group: d = 4*wid .. +3
    int lane = tid & 31;    // row within 32-row block

    float acc0 = 0.f, acc1 = 0.f, acc2 = 0.f, acc3 = 0.f;

    const float* Vb = V + (size_t)b * NSEQ * DIM;

    for (int jt = 0; jt < NSEQ; jt += 128) {
        __syncthreads();
        if (tid < 128) wt[tid] = g_w[b * NSEQ + jt + tid];
        __syncthreads();
        // Yt[j][d] = w[jt+j] * V[b][jt+j][d]   (2048 float4 / 512 threads = 4 each)
        #pragma unroll
        for (int t0 = 0; t0 < 4; ++t0) {
            int t = tid + t0 * 512;
            int j = t >> 4, dq = t & 15;
            float4 v4 = reinterpret_cast<const float4*>(Vb + (size_t)(jt + j) * DIM)[dq];
            float wv = wt[j];
            *reinterpret_cast<float4*>(&Yt[j*64 + dq*4]) =
                make_float4(v4.x*wv, v4.y*wv, v4.z*wv, v4.w*wv);
        }
        // Ssm[r][j] = S[b][i0+r][jt+j] as fp32   (4096 bf16 / 512 threads = 8 each)
        {
            const __nv_bfloat16* Sb2 = g_S + ((size_t)(b * NSEQ + i0) << 10) + jt;
            int r = tid >> 4, jq = tid & 15;
            uint4 v = *reinterpret_cast<const uint4*>(Sb2 + ((size_t)r << 10) + jq*8);
            float* dst = &Ssm[r*132 + jq*8];
            *reinterpret_cast<float4*>(dst)     = make_float4(bflo(v.x), bfhi(v.x), bflo(v.y), bfhi(v.y));
            *reinterpret_cast<float4*>(dst + 4) = make_float4(bflo(v.z), bfhi(v.z), bflo(v.w), bfhi(v.w));
        }
        __syncthreads();

        const float* srow = &Ssm[lane * 132];
        const float* ybase = &Yt[wid * 4];
        #pragma unroll 4
        for (int j4 = 0; j4 < 32; ++j4) {
            float4 s4 = *reinterpret_cast<const float4*>(srow + j4*4);
            float4 ya = *reinterpret_cast<const float4*>(ybase + (j4*4 + 0)*64);
            float4 yb = *reinterpret_cast<const float4*>(ybase + (j4*4 + 1)*64);
            float4 yc = *reinterpret_cast<const float4*>(ybase + (j4*4 + 2)*64);
            float4 yd = *reinterpret_cast<const float4*>(ybase + (j4*4 + 3)*64);
            acc0 = fmaf(s4.x, ya.x, acc0); acc1 = fmaf(s4.x, ya.y, acc1);
            acc2 = fmaf(s4.x, ya.z, acc2); acc3 = fmaf(s4.x, ya.w, acc3);
            acc0 = fmaf(s4.y, yb.x, acc0); acc1 = fmaf(s4.y, yb.y, acc1);
            acc2 = fmaf(s4.y, yb.z, acc2); acc3 = fmaf(s4.y, yb.w, acc3);
            acc0 = fmaf(s4.z, yc.x, acc0); acc1 = fmaf(s4.z, yc.y, acc1);
            acc2 = fmaf(s4.z, yc.z, acc2); acc3 = fmaf(s4.z, yc.w, acc3);
            acc0 = fmaf(s4.w, yd.x, acc0); acc1 = fmaf(s4.w, yd.y, acc1);
            acc2 = fmaf(s4.w, yd.z, acc2); acc3 = fmaf(s4.w, yd.w, acc3);
        }
    }

    int row = i0 + lane;
    float a = g_a[b * NSEQ + row];
    float4 v4 = *reinterpret_cast<const float4*>(&Vb[(size_t)row * DIM + wid*4]);
    float4 o;
    o.x = fmaf(acc0, a, v4.x);
    o.y = fmaf(acc1, a, v4.y);
    o.z = fmaf(acc2, a, v4.z);
    o.w = fmaf(acc3, a, v4.w);
    *reinterpret_cast<float4*>(&out[((size_t)b * NSEQ + row) * DIM + wid*4]) = o;
}

// ---------------- launcher ----------------
extern "C" void kernel_launch(void* const* d_in, const int* in_sizes, int n_in,
                              void* d_out, int out_size) {
    const float* q = (const float*)d_in[0];
    const float* k = (const float*)d_in[1];
    const float* V = (const float*)d_in[2];
    float* out = (float*)d_out;
    (void)in_sizes; (void)n_in; (void)out_size;

    const int outSmem = (128*64 + 32*132) * (int)sizeof(float);   // 49664

    cudaFuncSetAttribute(out_kernel, cudaFuncAttributeMaxDynamicSharedMemorySize, outSmem);
    cudaFuncSetAttribute(sink_kernel, cudaFuncAttributeNonPortableClusterSizeAllowed, 1);

    int csz = 8;
    {
        int maxC = 0;
        cudaLaunchConfig_t qcfg = {};
        qcfg.gridDim  = dim3(128);
        qcfg.blockDim = dim3(512);
        qcfg.dynamicSmemBytes = 0;
        if (cudaOccupancyMaxPotentialClusterSize(&maxC, sink_kernel, &qcfg) == cudaSuccess) {
            if (maxC >= 16) csz = 16;
        }
    }

    norm_kernel<<<2048, 256>>>(q, k);
    gemmS_kernel<<<dim3(32, 8), 256>>>();

    {
        cudaLaunchAttribute at;
        at.id = cudaLaunchAttributeClusterDimension;
        at.val.clusterDim.x = (unsigned)csz;
        at.val.clusterDim.y = 1;
        at.val.clusterDim.z = 1;
        cudaLaunchConfig_t cfg = {};
        cfg.gridDim  = dim3((unsigned)(BATCH * csz));
        cfg.blockDim = dim3(512);
        cfg.dynamicSmemBytes = 0;
        cfg.stream = 0;
        cfg.attrs = &at;
        cfg.numAttrs = 1;
        cudaLaunchKernelEx(&cfg, sink_kernel);
    }

    out_kernel<<<dim3(32, 8), 512, outSmem>>>(V, out);
}

// round 12
// speedup vs baseline: 1.5270x; 1.0399x over previous
#include <cuda_runtime.h>
#include <cuda_bf16.h>

// ---------------------------------------------------------------------------
// OT (Sinkhorn) attention, B=8, N=1024, D=64, fp32.
// Scaling-form Sinkhorn, fused row pass (R5-proven math). S slice resident in
// SHARED MEMORY during the 100-iteration loop (zero L2 traffic in steady state).
// bf16 S (16 MB) built once. One cluster per batch (16 CTAs if allowed).
// ---------------------------------------------------------------------------

#define BATCH 8
#define NSEQ  1024
#define DIM   64
#define EPS_F 0.05f
#define MU_F  (1.0f/1024.0f + 1e-8f)

__device__ __nv_bfloat16 g_S[(size_t)BATCH * NSEQ * NSEQ];   // 16 MB
__device__ float g_Qn[BATCH * NSEQ * DIM];
__device__ float g_Kn[BATCH * NSEQ * DIM];
__device__ float g_a[BATCH * NSEQ];
__device__ float g_w[BATCH * NSEQ];

// ---------------- helpers ----------------
__device__ __forceinline__ float bflo(unsigned x) { return __uint_as_float(x << 16); }
__device__ __forceinline__ float bfhi(unsigned x) { return __uint_as_float(x & 0xFFFF0000u); }

__device__ __forceinline__ unsigned pk2(float a, float b) {
    __nv_bfloat162 t = __floats2bfloat162_rn(a, b);  // .x = a (low)
    return *reinterpret_cast<unsigned*>(&t);
}

__device__ __forceinline__ unsigned smem_u32(const void* p) {
    unsigned a;
    asm("{ .reg .u64 t; cvta.to.shared.u64 t, %1; cvt.u32.u64 %0, t; }" : "=r"(a) : "l"(p));
    return a;
}
__device__ __forceinline__ unsigned cluster_rank() {
    unsigned r; asm("mov.u32 %0, %%cluster_ctarank;" : "=r"(r)); return r;
}
__device__ __forceinline__ unsigned cluster_nctas() {
    unsigned r; asm("mov.u32 %0, %%cluster_nctaid.x;" : "=r"(r)); return r;
}
__device__ __forceinline__ unsigned mapa_u32(unsigned addr, unsigned rank) {
    unsigned r; asm("mapa.shared::cluster.u32 %0, %1, %2;" : "=r"(r) : "r"(addr), "r"(rank));
    return r;
}
__device__ __forceinline__ float ld_dsmem_f32(unsigned addr) {
    float v; asm volatile("ld.shared::cluster.f32 %0, [%1];" : "=f"(v) : "r"(addr)); return v;
}
__device__ __forceinline__ void st_dsmem_f32(unsigned addr, float v) {
    asm volatile("st.shared::cluster.f32 [%0], %1;" :: "r"(addr), "f"(v));
}
#define CLUSTER_SYNC() do { \
    asm volatile("barrier.cluster.arrive.aligned;" ::: "memory"); \
    asm volatile("barrier.cluster.wait.aligned;"   ::: "memory"); \
} while (0)

// ---------------- kernel 1: L2-normalize rows of q,k ----------------
__global__ void __launch_bounds__(256) norm_kernel(const float* __restrict__ q,
                                                   const float* __restrict__ k) {
    int gw   = (blockIdx.x * 256 + threadIdx.x) >> 5;
    int lane = threadIdx.x & 31;
    const float* src;
    float* dst;
    if (gw < BATCH * NSEQ) { src = q + (size_t)gw * DIM;                dst = g_Qn + (size_t)gw * DIM; }
    else                   { src = k + (size_t)(gw - BATCH*NSEQ) * DIM; dst = g_Kn + (size_t)(gw - BATCH*NSEQ) * DIM; }
    float2 v = reinterpret_cast<const float2*>(src)[lane];
    float s = v.x * v.x + v.y * v.y;
    #pragma unroll
    for (int o = 16; o > 0; o >>= 1) s += __shfl_xor_sync(~0u, s, o);
    float n   = sqrtf(s);
    float inv = 1.0f / fmaxf(n, 1e-12f);
    reinterpret_cast<float2*>(dst)[lane] = make_float2(v.x * inv, v.y * inv);
}

// ---------------- kernel 2: S = exp((QK^T - 1)/eps), bf16 ----------------
__global__ void __launch_bounds__(256) gemmS_kernel() {
    int b  = blockIdx.y;
    int i0 = blockIdx.x * 32;
    __shared__ __align__(16) float Qs[32][DIM];
    __shared__ __align__(16) float Ks[128][DIM];

    const float* Qp = g_Qn + (size_t)(b * NSEQ + i0) * DIM;
    for (int t = threadIdx.x; t < 32 * DIM / 4; t += 256)
        reinterpret_cast<float4*>(&Qs[0][0])[t] = reinterpret_cast<const float4*>(Qp)[t];

    int ti = threadIdx.x >> 5;
    int tj = threadIdx.x & 31;

    for (int jt = 0; jt < NSEQ; jt += 128) {
        __syncthreads();
        const float* Kp = g_Kn + (size_t)(b * NSEQ + jt) * DIM;
        for (int t = threadIdx.x; t < 128 * DIM / 4; t += 256)
            reinterpret_cast<float4*>(&Ks[0][0])[t] = reinterpret_cast<const float4*>(Kp)[t];
        __syncthreads();

        float acc[4][4];
        #pragma unroll
        for (int r = 0; r < 4; ++r)
            #pragma unroll
            for (int c = 0; c < 4; ++c) acc[r][c] = 0.f;

        #pragma unroll
        for (int d = 0; d < DIM; d += 4) {
            float4 qv[4], kv[4];
            #pragma unroll
            for (int r = 0; r < 4; ++r) qv[r] = *reinterpret_cast<const float4*>(&Qs[4*ti + r][d]);
            #pragma unroll
            for (int c = 0; c < 4; ++c) kv[c] = *reinterpret_cast<const float4*>(&Ks[4*tj + c][d]);
            #pragma unroll
            for (int r = 0; r < 4; ++r)
                #pragma unroll
                for (int c = 0; c < 4; ++c) {
                    acc[r][c] = fmaf(qv[r].x, kv[c].x, acc[r][c]);
                    acc[r][c] = fmaf(qv[r].y, kv[c].y, acc[r][c]);
                    acc[r][c] = fmaf(qv[r].z, kv[c].z, acc[r][c]);
                    acc[r][c] = fmaf(qv[r].w, kv[c].w, acc[r][c]);
                }
        }

        #pragma unroll
        for (int r = 0; r < 4; ++r) {
            size_t rowi = (size_t)(b * NSEQ + i0 + 4*ti + r);
            float e0 = __expf(20.0f * (acc[r][0] - 1.0f));
            float e1 = __expf(20.0f * (acc[r][1] - 1.0f));
            float e2 = __expf(20.0f * (acc[r][2] - 1.0f));
            float e3 = __expf(20.0f * (acc[r][3] - 1.0f));
            uint2 p = make_uint2(pk2(e0, e1), pk2(e2, e3));
            *reinterpret_cast<uint2*>(g_S + (rowi << 10) + jt + 4*tj) = p;
        }
    }
}

// ---------------- kernel 3: fused Sinkhorn loop, SMEM-resident S ----------------
// grid = BATCH * csz CTAs, one csz-CTA cluster per batch, 512 threads.
// dynamic smem (floats): sw[1024] | spc[1024] | redbuf[8][1024] | Ssm (64 rows x 2KB)
__global__ void __launch_bounds__(512) sink_kernel() {
    extern __shared__ __align__(16) float dynS[];
    float* sw     = dynS;                 // 4 KB
    float* spc    = dynS + 1024;          // 4 KB
    float* redbuf = dynS + 2048;          // [8][1024] 32 KB
    uint4* SsmV   = reinterpret_cast<uint4*>(dynS + 10240);  // 128 KB (64 rows x 128 uint4)

    __shared__ float sa[128];
    __shared__ float swErr[16];
    __shared__ float sErrTot;
    __shared__ int   sBreak;

    unsigned csz  = cluster_nctas();          // 8 or 16
    unsigned rank = cluster_rank();
    int b           = blockIdx.x / (int)csz;
    int rowsPerCta  = NSEQ / (int)csz;        // 128 or 64
    int rowsPerWarp = rowsPerCta >> 4;        // 8 or 4
    int colsPerCta  = NSEQ / (int)csz;
    int rowsInS     = rowsPerCta < 64 ? rowsPerCta : 64;   // smem-resident rows
    int tid  = threadIdx.x;
    int wid  = tid >> 5;
    int lane = tid & 31;

    for (int t = tid; t < NSEQ; t += 512) sw[t] = 1.0f;
    if (tid < rowsPerCta) sa[tid] = 1.0f;
    if (tid == 0) sBreak = 0;

    const __nv_bfloat16* Sbase = g_S + ((size_t)(b * NSEQ + (int)rank * rowsPerCta) << 10);

    // ---- preload S rows [0, rowsInS) into shared memory (contiguous slice)
    {
        const uint4* src = reinterpret_cast<const uint4*>(Sbase);
        int nvec = rowsInS * 128;   // 128 uint4 per row
        for (int t = tid; t < nvec; t += 512) SsmV[t] = src[t];
    }
    __syncthreads();

    unsigned spc_u32 = smem_u32(spc);
    unsigned sw_u32  = smem_u32(sw);
    unsigned err_u32 = smem_u32(&sErrTot);

    #pragma unroll 1
    for (int iter = 0; iter < 100; ++iter) {
        // preload w: lane covers cols {c*256 + lane*8 + e}
        float wr[4][8];
        #pragma unroll
        for (int c = 0; c < 4; ++c) {
            float4 w0 = *reinterpret_cast<const float4*>(&sw[c*256 + lane*8]);
            float4 w1 = *reinterpret_cast<const float4*>(&sw[c*256 + lane*8 + 4]);
            wr[c][0] = w0.x; wr[c][1] = w0.y; wr[c][2] = w0.z; wr[c][3] = w0.w;
            wr[c][4] = w1.x; wr[c][5] = w1.y; wr[c][6] = w1.z; wr[c][7] = w1.w;
        }

        float cc[4][8];
        #pragma unroll
        for (int c = 0; c < 4; ++c)
            #pragma unroll
            for (int e = 0; e < 8; ++e) cc[c][e] = 0.f;

        float errAcc = 0.f;

        // process one resident row: dot -> a_new -> rank-1
        auto process = [&](const uint4 (&v)[4], int row) {
            float a0 = 0.f, a1 = 0.f, a2 = 0.f, a3 = 0.f;
            #pragma unroll
            for (int c = 0; c < 4; ++c) {
                a0 = fmaf(bflo(v[c].x), wr[c][0], a0); a1 = fmaf(bfhi(v[c].x), wr[c][1], a1);
                a2 = fmaf(bflo(v[c].y), wr[c][2], a2); a3 = fmaf(bfhi(v[c].y), wr[c][3], a3);
                a0 = fmaf(bflo(v[c].z), wr[c][4], a0); a1 = fmaf(bfhi(v[c].z), wr[c][5], a1);
                a2 = fmaf(bflo(v[c].w), wr[c][6], a2); a3 = fmaf(bfhi(v[c].w), wr[c][7], a3);
            }
            float acc = (a0 + a1) + (a2 + a3);
            #pragma unroll
            for (int o = 16; o > 0; o >>= 1) acc += __shfl_xor_sync(~0u, acc, o);
            float anew = MU_F / acc;   // all lanes
            if (lane == 0) {
                float aold = sa[row];
                sa[row] = anew;
                errAcc += fabsf(EPS_F * (__logf(anew) - __logf(aold)));
            }
            #pragma unroll
            for (int c = 0; c < 4; ++c) {
                cc[c][0] = fmaf(bflo(v[c].x), anew, cc[c][0]);
                cc[c][1] = fmaf(bfhi(v[c].x), anew, cc[c][1]);
                cc[c][2] = fmaf(bflo(v[c].y), anew, cc[c][2]);
                cc[c][3] = fmaf(bfhi(v[c].y), anew, cc[c][3]);
                cc[c][4] = fmaf(bflo(v[c].z), anew, cc[c][4]);
                cc[c][5] = fmaf(bfhi(v[c].z), anew, cc[c][5]);
                cc[c][6] = fmaf(bflo(v[c].w), anew, cc[c][6]);
                cc[c][7] = fmaf(bfhi(v[c].w), anew, cc[c][7]);
            }
        };

        // ---- fused pass over this warp's rows (smem path or global path)
        int row0 = wid * rowsPerWarp;
        if (row0 + rowsPerWarp <= rowsInS) {
            #pragma unroll 1
            for (int r8 = 0; r8 < rowsPerWarp; ++r8) {
                int row = row0 + r8;
                const uint4* p = SsmV + row * 128;
                uint4 v[4];
                #pragma unroll
                for (int c = 0; c < 4; ++c) v[c] = p[c*32 + lane];
                process(v, row);
            }
        } else {
            #pragma unroll 1
            for (int r8 = 0; r8 < rowsPerWarp; ++r8) {
                int row = row0 + r8;
                const uint4* p = reinterpret_cast<const uint4*>(Sbase + ((size_t)row << 10));
                uint4 v[4];
                #pragma unroll
                for (int c = 0; c < 4; ++c) v[c] = p[c*32 + lane];
                process(v, row);
            }
        }
        if (lane == 0) swErr[wid] = errAcc;

        // ---- warp tree: 16 -> 1 column-accumulator reduction
        #pragma unroll
        for (int h = 8; h >= 1; h >>= 1) {
            if (wid >= h && wid < 2*h) {
                #pragma unroll
                for (int c = 0; c < 4; ++c) {
                    float* dst = &redbuf[(wid - h)*1024 + c*256 + lane*8];
                    *reinterpret_cast<float4*>(dst)     = make_float4(cc[c][0], cc[c][1], cc[c][2], cc[c][3]);
                    *reinterpret_cast<float4*>(dst + 4) = make_float4(cc[c][4], cc[c][5], cc[c][6], cc[c][7]);
                }
            }
            __syncthreads();
            if (wid < h) {
                #pragma unroll
                for (int c = 0; c < 4; ++c) {
                    const float* src = &redbuf[wid*1024 + c*256 + lane*8];
                    float4 s0 = *reinterpret_cast<const float4*>(src);
                    float4 s1 = *reinterpret_cast<const float4*>(src + 4);
                    cc[c][0] += s0.x; cc[c][1] += s0.y; cc[c][2] += s0.z; cc[c][3] += s0.w;
                    cc[c][4] += s1.x; cc[c][5] += s1.y; cc[c][6] += s1.z; cc[c][7] += s1.w;
                }
            }
            __syncthreads();
        }
        if (wid == 0) {
            #pragma unroll
            for (int c = 0; c < 4; ++c) {
                float* dst = &spc[c*256 + lane*8];
                *reinterpret_cast<float4*>(dst)     = make_float4(cc[c][0], cc[c][1], cc[c][2], cc[c][3]);
                *reinterpret_cast<float4*>(dst + 4) = make_float4(cc[c][4], cc[c][5], cc[c][6], cc[c][7]);
            }
        }
        if (tid == 0) {
            float e = 0.f;
            #pragma unroll
            for (int t2 = 0; t2 < 16; ++t2) e += swErr[t2];
            sErrTot = e;
        }
        __syncthreads();
        CLUSTER_SYNC();   // spc / sErrTot visible cluster-wide

        // ---- cross-CTA column reduce + w broadcast (rank owns colsPerCta cols)
        if (tid < colsPerCta) {
            int col = (int)rank * colsPerCta + tid;
            float cs = 0.f;
            if (csz == 16) {
                #pragma unroll
                for (unsigned r2 = 0; r2 < 16; ++r2)
                    cs += ld_dsmem_f32(mapa_u32(spc_u32 + 4u*col, r2));
                float wnew = MU_F / cs;
                #pragma unroll
                for (unsigned r2 = 0; r2 < 16; ++r2)
                    st_dsmem_f32(mapa_u32(sw_u32 + 4u*col, r2), wnew);
            } else {
                for (unsigned r2 = 0; r2 < csz; ++r2)
                    cs += ld_dsmem_f32(mapa_u32(spc_u32 + 4u*col, r2));
                float wnew = MU_F / cs;
                for (unsigned r2 = 0; r2 < csz; ++r2)
                    st_dsmem_f32(mapa_u32(sw_u32 + 4u*col, r2), wnew);
            }
        } else if (tid == colsPerCta) {
            float e = 0.f;
            for (unsigned r2 = 0; r2 < csz; ++r2)
                e += ld_dsmem_f32(mapa_u32(err_u32, r2));
            sBreak = (e < 1.28e-4f) ? 1 : 0;   // stricter than ref's global break
        }
        CLUSTER_SYNC();
        if (sBreak) break;
    }

    if (tid < rowsPerCta)
        g_a[b * NSEQ + (int)rank * rowsPerCta + tid] = sa[tid];
    if (tid < colsPerCta)
        g_w[b * NSEQ + (int)rank * colsPerCta + tid] = sw[(int)rank * colsPerCta + tid];
}

// ---------------- kernel 4: out = a (.) (S (w (.) V)) + V ----------------
// grid (32, 8): 32-row blocks x batch, 512 threads (16 warps), 2 CTAs/SM.
__global__ void __launch_bounds__(512) out_kernel(const float* __restrict__ V,
                                                  float* __restrict__ out) {
    int b  = blockIdx.y;
    int i0 = blockIdx.x * 32;
    extern __shared__ float dynO[];
    float* Yt  = dynO;              // [128][64] fp32, 32 KB
    float* Ssm = dynO + 128*64;     // [32][132] fp32, 16.5 KB
    __shared__ float wt[128];

    int tid  = threadIdx.x;
    int wid  = tid >> 5;    // d-group: d = 4*wid .. +3
    int lane = tid & 31;    // row within 32-row block

    float acc0 = 0.f, acc1 = 0.f, acc2 = 0.f, acc3 = 0.f;

    const float* Vb = V + (size_t)b * NSEQ * DIM;

    for (int jt = 0; jt < NSEQ; jt += 128) {
        __syncthreads();
        if (tid < 128) wt[tid] = g_w[b * NSEQ + jt + tid];
        __syncthreads();
        #pragma unroll
        for (int t0 = 0; t0 < 4; ++t0) {
            int t = tid + t0 * 512;
            int j = t >> 4, dq = t & 15;
            float4 v4 = reinterpret_cast<const float4*>(Vb + (size_t)(jt + j) * DIM)[dq];
            float wv = wt[j];
            *reinterpret_cast<float4*>(&Yt[j*64 + dq*4]) =
                make_float4(v4.x*wv, v4.y*wv, v4.z*wv, v4.w*wv);
        }
        {
            const __nv_bfloat16* Sb2 = g_S + ((size_t)(b * NSEQ + i0) << 10) + jt;
            int r = tid >> 4, jq = tid & 15;
            uint4 v = *reinterpret_cast<const uint4*>(Sb2 + ((size_t)r << 10) + jq*8);
            float* dst = &Ssm[r*132 + jq*8];
            *reinterpret_cast<float4*>(dst)     = make_float4(bflo(v.x), bfhi(v.x), bflo(v.y), bfhi(v.y));
            *reinterpret_cast<float4*>(dst + 4) = make_float4(bflo(v.z), bfhi(v.z), bflo(v.w), bfhi(v.w));
        }
        __syncthreads();

        const float* srow = &Ssm[lane * 132];
        const float* ybase = &Yt[wid * 4];
        #pragma unroll 4
        for (int j4 = 0; j4 < 32; ++j4) {
            float4 s4 = *reinterpret_cast<const float4*>(srow + j4*4);
            float4 ya = *reinterpret_cast<const float4*>(ybase + (j4*4 + 0)*64);
            float4 yb = *reinterpret_cast<const float4*>(ybase + (j4*4 + 1)*64);
            float4 yc = *reinterpret_cast<const float4*>(ybase + (j4*4 + 2)*64);
            float4 yd = *reinterpret_cast<const float4*>(ybase + (j4*4 + 3)*64);
            acc0 = fmaf(s4.x, ya.x, acc0); acc1 = fmaf(s4.x, ya.y, acc1);
            acc2 = fmaf(s4.x, ya.z, acc2); acc3 = fmaf(s4.x, ya.w, acc3);
            acc0 = fmaf(s4.y, yb.x, acc0); acc1 = fmaf(s4.y, yb.y, acc1);
            acc2 = fmaf(s4.y, yb.z, acc2); acc3 = fmaf(s4.y, yb.w, acc3);
            acc0 = fmaf(s4.z, yc.x, acc0); acc1 = fmaf(s4.z, yc.y, acc1);
            acc2 = fmaf(s4.z, yc.z, acc2); acc3 = fmaf(s4.z, yc.w, acc3);
            acc0 = fmaf(s4.w, yd.x, acc0); acc1 = fmaf(s4.w, yd.y, acc1);
            acc2 = fmaf(s4.w, yd.z, acc2); acc3 = fmaf(s4.w, yd.w, acc3);
        }
    }

    int row = i0 + lane;
    float a = g_a[b * NSEQ + row];
    float4 v4 = *reinterpret_cast<const float4*>(&Vb[(size_t)row * DIM + wid*4]);
    float4 o;
    o.x = fmaf(acc0, a, v4.x);
    o.y = fmaf(acc1, a, v4.y);
    o.z = fmaf(acc2, a, v4.z);
    o.w = fmaf(acc3, a, v4.w);
    *reinterpret_cast<float4*>(&out[((size_t)b * NSEQ + row) * DIM + wid*4]) = o;
}

// ---------------- launcher ----------------
extern "C" void kernel_launch(void* const* d_in, const int* in_sizes, int n_in,
                              void* d_out, int out_size) {
    const float* q = (const float*)d_in[0];
    const float* k = (const float*)d_in[1];
    const float* V = (const float*)d_in[2];
    float* out = (float*)d_out;
    (void)in_sizes; (void)n_in; (void)out_size;

    const int outSmem  = (128*64 + 32*132) * (int)sizeof(float);      // 49664
    const int sinkSmem = 10240 * (int)sizeof(float) + 64 * 2048;      // 40960 + 131072 = 172032

    cudaFuncSetAttribute(out_kernel,  cudaFuncAttributeMaxDynamicSharedMemorySize, outSmem);
    cudaFuncSetAttribute(sink_kernel, cudaFuncAttributeMaxDynamicSharedMemorySize, sinkSmem);
    cudaFuncSetAttribute(sink_kernel, cudaFuncAttributeNonPortableClusterSizeAllowed, 1);

    int csz = 8;
    {
        int maxC = 0;
        cudaLaunchConfig_t qcfg = {};
        qcfg.gridDim  = dim3(128);
        qcfg.blockDim = dim3(512);
        qcfg.dynamicSmemBytes = sinkSmem;
        if (cudaOccupancyMaxPotentialClusterSize(&maxC, sink_kernel, &qcfg) == cudaSuccess) {
            if (maxC >= 16) csz = 16;
        }
    }

    norm_kernel<<<2048, 256>>>(q, k);
    gemmS_kernel<<<dim3(32, 8), 256>>>();

    {
        cudaLaunchAttribute at;
        at.id = cudaLaunchAttributeClusterDimension;
        at.val.clusterDim.x = (unsigned)csz;
        at.val.clusterDim.y = 1;
        at.val.clusterDim.z = 1;
        cudaLaunchConfig_t cfg = {};
        cfg.gridDim  = dim3((unsigned)(BATCH * csz));
        cfg.blockDim = dim3(512);
        cfg.dynamicSmemBytes = sinkSmem;
        cfg.stream = 0;
        cfg.attrs = &at;
        cfg.numAttrs = 1;
        cudaLaunchKernelEx(&cfg, sink_kernel);
    }

    out_kernel<<<dim3(32, 8), 512, outSmem>>>(V, out);
}

// round 15
// speedup vs baseline: 1.5398x; 1.0084x over previous
#include <cuda_runtime.h>
#include <cuda_bf16.h>

// ---------------------------------------------------------------------------
// OT (Sinkhorn) attention, B=8, N=1024, D=64, fp32.
// Scaling-form Sinkhorn, fused row pass, SMEM-resident S slice, single-stage
// column reduce, b64 cluster exchange. f32x2 packed FMA in gemmS/out.
// ---------------------------------------------------------------------------

#define BATCH 8
#define NSEQ  1024
#define DIM   64
#define EPS_F 0.05f
#define MU_F  (1.0f/1024.0f + 1e-8f)

typedef unsigned long long ull;

__device__ __nv_bfloat16 g_S[(size_t)BATCH * NSEQ * NSEQ];   // 16 MB
__device__ float g_Qn[BATCH * NSEQ * DIM];
__device__ float g_Kn[BATCH * NSEQ * DIM];
__device__ float g_a[BATCH * NSEQ];
__device__ float g_w[BATCH * NSEQ];

// ---------------- helpers ----------------
__device__ __forceinline__ float bflo(unsigned x) { return __uint_as_float(x << 16); }
__device__ __forceinline__ float bfhi(unsigned x) { return __uint_as_float(x & 0xFFFF0000u); }

__device__ __forceinline__ unsigned pk2(float a, float b) {
    __nv_bfloat162 t = __floats2bfloat162_rn(a, b);  // .x = a (low)
    return *reinterpret_cast<unsigned*>(&t);
}

// ---- packed f32x2 ----
__device__ __forceinline__ ull fma2(ull a, ull b, ull c) {
    ull d; asm("fma.rn.f32x2 %0, %1, %2, %3;" : "=l"(d) : "l"(a), "l"(b), "l"(c)); return d;
}
__device__ __forceinline__ ull add2(ull a, ull b) {
    ull d; asm("add.rn.f32x2 %0, %1, %2;" : "=l"(d) : "l"(a), "l"(b)); return d;
}
__device__ __forceinline__ ull pack2u(unsigned lo, unsigned hi) {
    ull r; asm("mov.b64 %0, {%1, %2};" : "=l"(r) : "r"(lo), "r"(hi)); return r;
}
__device__ __forceinline__ void unpack2(ull p, float& lo, float& hi) {
    unsigned a, b;
    asm("mov.b64 {%0, %1}, %2;" : "=r"(a), "=r"(b) : "l"(p));
    lo = __uint_as_float(a); hi = __uint_as_float(b);
}
__device__ __forceinline__ ull dup2(float s) {
    unsigned u = __float_as_uint(s);
    return pack2u(u, u);
}

__device__ __forceinline__ unsigned smem_u32(const void* p) {
    unsigned a;
    asm("{ .reg .u64 t; cvta.to.shared.u64 t, %1; cvt.u32.u64 %0, t; }" : "=r"(a) : "l"(p));
    return a;
}
__device__ __forceinline__ unsigned cluster_rank() {
    unsigned r; asm("mov.u32 %0, %%cluster_ctarank;" : "=r"(r)); return r;
}
__device__ __forceinline__ unsigned cluster_nctas() {
    unsigned r; asm("mov.u32 %0, %%cluster_nctaid.x;" : "=r"(r)); return r;
}
__device__ __forceinline__ unsigned mapa_u32(unsigned addr, unsigned rank) {
    unsigned r; asm("mapa.shared::cluster.u32 %0, %1, %2;" : "=r"(r) : "r"(addr), "r"(rank));
    return r;
}
__device__ __forceinline__ float ld_dsmem_f32(unsigned addr) {
    float v; asm volatile("ld.shared::cluster.f32 %0, [%1];" : "=f"(v) : "r"(addr)); return v;
}
__device__ __forceinline__ ull ld_dsmem_b64(unsigned addr) {
    ull v; asm volatile("ld.shared::cluster.b64 %0, [%1];" : "=l"(v) : "r"(addr)); return v;
}
__device__ __forceinline__ void st_dsmem_b64(unsigned addr, ull v) {
    asm volatile("st.shared::cluster.b64 [%0], %1;" :: "r"(addr), "l"(v));
}
#define CLUSTER_SYNC() do { \
    asm volatile("barrier.cluster.arrive.aligned;" ::: "memory"); \
    asm volatile("barrier.cluster.wait.aligned;"   ::: "memory"); \
} while (0)

// ---------------- kernel 1: L2-normalize rows of q,k ----------------
__global__ void __launch_bounds__(256) norm_kernel(const float* __restrict__ q,
                                                   const float* __restrict__ k) {
    int gw   = (blockIdx.x * 256 + threadIdx.x) >> 5;
    int lane = threadIdx.x & 31;
    const float* src;
    float* dst;
    if (gw < BATCH * NSEQ) { src = q + (size_t)gw * DIM;                dst = g_Qn + (size_t)gw * DIM; }
    else                   { src = k + (size_t)(gw - BATCH*NSEQ) * DIM; dst = g_Kn + (size_t)(gw - BATCH*NSEQ) * DIM; }
    float2 v = reinterpret_cast<const float2*>(src)[lane];
    float s = v.x * v.x + v.y * v.y;
    #pragma unroll
    for (int o = 16; o > 0; o >>= 1) s += __shfl_xor_sync(~0u, s, o);
    float n   = sqrtf(s);
    float inv = 1.0f / fmaxf(n, 1e-12f);
    reinterpret_cast<float2*>(dst)[lane] = make_float2(v.x * inv, v.y * inv);
}

// ---------------- kernel 2: S = exp((QK^T - 1)/eps), bf16; f32x2 packed ----------------
__global__ void __launch_bounds__(256) gemmS_kernel() {
    int b  = blockIdx.y;
    int i0 = blockIdx.x * 32;
    __shared__ __align__(16) float Qs[32][DIM];
    __shared__ __align__(16) float Ks[128][DIM];

    const float* Qp = g_Qn + (size_t)(b * NSEQ + i0) * DIM;
    for (int t = threadIdx.x; t < 32 * DIM / 4; t += 256)
        reinterpret_cast<float4*>(&Qs[0][0])[t] = reinterpret_cast<const float4*>(Qp)[t];

    int ti = threadIdx.x >> 5;
    int tj = threadIdx.x & 31;

    for (int jt = 0; jt < NSEQ; jt += 128) {
        __syncthreads();
        const float* Kp = g_Kn + (size_t)(b * NSEQ + jt) * DIM;
        for (int t = threadIdx.x; t < 128 * DIM / 4; t += 256)
            reinterpret_cast<float4*>(&Ks[0][0])[t] = reinterpret_cast<const float4*>(Kp)[t];
        __syncthreads();

        ull accp[4][4];
        #pragma unroll
        for (int r = 0; r < 4; ++r)
            #pragma unroll
            for (int c = 0; c < 4; ++c) accp[r][c] = 0ull;

        #pragma unroll
        for (int d = 0; d < DIM; d += 4) {
            ulonglong2 qp[4], kp[4];
            #pragma unroll
            for (int r = 0; r < 4; ++r) qp[r] = *reinterpret_cast<const ulonglong2*>(&Qs[4*ti + r][d]);
            #pragma unroll
            for (int c = 0; c < 4; ++c) kp[c] = *reinterpret_cast<const ulonglong2*>(&Ks[4*tj + c][d]);
            #pragma unroll
            for (int r = 0; r < 4; ++r)
                #pragma unroll
                for (int c = 0; c < 4; ++c) {
                    accp[r][c] = fma2(qp[r].x, kp[c].x, accp[r][c]);
                    accp[r][c] = fma2(qp[r].y, kp[c].y, accp[r][c]);
                }
        }

        #pragma unroll
        for (int r = 0; r < 4; ++r) {
            size_t rowi = (size_t)(b * NSEQ + i0 + 4*ti + r);
            float e[4];
            #pragma unroll
            for (int c = 0; c < 4; ++c) {
                float lo, hi; unpack2(accp[r][c], lo, hi);
                e[c] = __expf(20.0f * ((lo + hi) - 1.0f));
            }
            uint2 p = make_uint2(pk2(e[0], e[1]), pk2(e[2], e[3]));
            *reinterpret_cast<uint2*>(g_S + (rowi << 10) + jt + 4*tj) = p;
        }
    }
}

// ---------------- kernel 3: fused Sinkhorn loop ----------------
// grid = BATCH * csz CTAs, cluster per batch, 512 threads.
// dyn smem (floats): sw[1024] | spc[1024] | wbuf[16][1024] | Ssm (<=72 rows x 2KB)
__global__ void __launch_bounds__(512) sink_kernel() {
    extern __shared__ __align__(16) float dynS[];
    float* sw   = dynS;                  // 4 KB
    float* spc  = dynS + 1024;           // 4 KB
    float* wbuf = dynS + 2048;           // 64 KB: [16][1024]
    uint4* SsmV = reinterpret_cast<uint4*>(dynS + 18432);  // up to 144 KB

    __shared__ float sa[128];
    __shared__ float swErr[16];
    __shared__ float sErrTot;
    __shared__ int   sBreak;

    unsigned csz  = cluster_nctas();          // 8 or 16
    unsigned rank = cluster_rank();
    int b           = blockIdx.x / (int)csz;
    int rowsPerCta  = NSEQ / (int)csz;        // 128 or 64
    int rowsPerWarp = rowsPerCta >> 4;        // 8 or 4
    int colsPerCta  = NSEQ / (int)csz;
    int rowsInS     = (csz == 16) ? 64 : 72;  // smem-resident rows
    int tid  = threadIdx.x;
    int wid  = tid >> 5;
    int lane = tid & 31;

    for (int t = tid; t < NSEQ; t += 512) sw[t] = 1.0f;
    if (tid < rowsPerCta) sa[tid] = 1.0f;
    if (tid == 0) sBreak = 0;

    const __nv_bfloat16* Sbase = g_S + ((size_t)(b * NSEQ + (int)rank * rowsPerCta) << 10);

    // preload S rows [0, rowsInS) into shared memory
    {
        const uint4* src = reinterpret_cast<const uint4*>(Sbase);
        int nvec = rowsInS * 128;
        for (int t = tid; t < nvec; t += 512) SsmV[t] = src[t];
    }
    __syncthreads();

    unsigned spc_u32 = smem_u32(spc);
    unsigned sw_u32  = smem_u32(sw);
    unsigned err_u32 = smem_u32(&sErrTot);

    #pragma unroll 1
    for (int iter = 0; iter < 100; ++iter) {
        // preload w: lane covers cols {c*256 + lane*8 + e}
        float wr[4][8];
        #pragma unroll
        for (int c = 0; c < 4; ++c) {
            float4 w0 = *reinterpret_cast<const float4*>(&sw[c*256 + lane*8]);
            float4 w1 = *reinterpret_cast<const float4*>(&sw[c*256 + lane*8 + 4]);
            wr[c][0] = w0.x; wr[c][1] = w0.y; wr[c][2] = w0.z; wr[c][3] = w0.w;
            wr[c][4] = w1.x; wr[c][5] = w1.y; wr[c][6] = w1.z; wr[c][7] = w1.w;
        }

        float cc[4][8];
        #pragma unroll
        for (int c = 0; c < 4; ++c)
            #pragma unroll
            for (int e = 0; e < 8; ++e) cc[c][e] = 0.f;

        float errAcc = 0.f;

        auto process = [&](const uint4 (&v)[4], int row) {
            float a0 = 0.f, a1 = 0.f, a2 = 0.f, a3 = 0.f;
            #pragma unroll
            for (int c = 0; c < 4; ++c) {
                a0 = fmaf(bflo(v[c].x), wr[c][0], a0); a1 = fmaf(bfhi(v[c].x), wr[c][1], a1);
                a2 = fmaf(bflo(v[c].y), wr[c][2], a2); a3 = fmaf(bfhi(v[c].y), wr[c][3], a3);
                a0 = fmaf(bflo(v[c].z), wr[c][4], a0); a1 = fmaf(bfhi(v[c].z), wr[c][5], a1);
                a2 = fmaf(bflo(v[c].w), wr[c][6], a2); a3 = fmaf(bfhi(v[c].w), wr[c][7], a3);
            }
            float acc = (a0 + a1) + (a2 + a3);
            #pragma unroll
            for (int o = 16; o > 0; o >>= 1) acc += __shfl_xor_sync(~0u, acc, o);
            float anew = MU_F / acc;
            if (lane == 0) {
                float aold = sa[row];
                sa[row] = anew;
                errAcc += fabsf(EPS_F * (__logf(anew) - __logf(aold)));
            }
            #pragma unroll
            for (int c = 0; c < 4; ++c) {
                cc[c][0] = fmaf(bflo(v[c].x), anew, cc[c][0]);
                cc[c][1] = fmaf(bfhi(v[c].x), anew, cc[c][1]);
                cc[c][2] = fmaf(bflo(v[c].y), anew, cc[c][2]);
                cc[c][3] = fmaf(bfhi(v[c].y), anew, cc[c][3]);
                cc[c][4] = fmaf(bflo(v[c].z), anew, cc[c][4]);
                cc[c][5] = fmaf(bfhi(v[c].z), anew, cc[c][5]);
                cc[c][6] = fmaf(bflo(v[c].w), anew, cc[c][6]);
                cc[c][7] = fmaf(bfhi(v[c].w), anew, cc[c][7]);
            }
        };

        int row0 = wid * rowsPerWarp;
        if (row0 + rowsPerWarp <= rowsInS) {
            #pragma unroll 1
            for (int r8 = 0; r8 < rowsPerWarp; ++r8) {
                int row = row0 + r8;
                const uint4* p = SsmV + row * 128;
                uint4 v[4];
                #pragma unroll
                for (int c = 0; c < 4; ++c) v[c] = p[c*32 + lane];
                process(v, row);
            }
        } else {
            #pragma unroll 1
            for (int r8 = 0; r8 < rowsPerWarp; ++r8) {
                int row = row0 + r8;
                const uint4* p = reinterpret_cast<const uint4*>(Sbase + ((size_t)row << 10));
                uint4 v[4];
                #pragma unroll
                for (int c = 0; c < 4; ++c) v[c] = p[c*32 + lane];
                process(v, row);
            }
        }
        if (lane == 0) swErr[wid] = errAcc;

        // ---- store warp partials to wbuf (full 1024-col coverage per warp)
        #pragma unroll
        for (int c = 0; c < 4; ++c) {
            float* dst = &wbuf[wid*1024 + c*256 + lane*8];
            *reinterpret_cast<float4*>(dst)     = make_float4(cc[c][0], cc[c][1], cc[c][2], cc[c][3]);
            *reinterpret_cast<float4*>(dst + 4) = make_float4(cc[c][4], cc[c][5], cc[c][6], cc[c][7]);
        }
        __syncthreads();

        // ---- single-stage reduce: each thread sums a column PAIR over 16 warps
        {
            int col0 = tid * 2;
            ull s = 0ull;
            #pragma unroll
            for (int wu = 0; wu < 16; ++wu) {
                ull x = *reinterpret_cast<const ull*>(&wbuf[wu*1024 + col0]);
                s = add2(s, x);
            }
            *reinterpret_cast<ull*>(&spc[col0]) = s;
        }
        if (tid == 0) {
            float e = 0.f;
            #pragma unroll
            for (int t2 = 0; t2 < 16; ++t2) e += swErr[t2];
            sErrTot = e;
        }
        CLUSTER_SYNC();   // spc / sErrTot visible cluster-wide

        // ---- cross-CTA: rank owns colsPerCta cols; b64 pair exchange
        int nPair = colsPerCta >> 1;
        if (tid < nPair) {
            int col2 = (int)rank * colsPerCta + tid * 2;
            unsigned off = 4u * (unsigned)col2;
            ull cs = 0ull;
            if (csz == 16) {
                #pragma unroll
                for (unsigned r2 = 0; r2 < 16; ++r2)
                    cs = add2(cs, ld_dsmem_b64(mapa_u32(spc_u32 + off, r2)));
            } else {
                for (unsigned r2 = 0; r2 < csz; ++r2)
                    cs = add2(cs, ld_dsmem_b64(mapa_u32(spc_u32 + off, r2)));
            }
            float c0, c1; unpack2(cs, c0, c1);
            float w0 = MU_F / c0;
            float w1 = MU_F / c1;
            ull wv = pack2u(__float_as_uint(w0), __float_as_uint(w1));
            if (csz == 16) {
                #pragma unroll
                for (unsigned r2 = 0; r2 < 16; ++r2)
                    st_dsmem_b64(mapa_u32(sw_u32 + off, r2), wv);
            } else {
                for (unsigned r2 = 0; r2 < csz; ++r2)
                    st_dsmem_b64(mapa_u32(sw_u32 + off, r2), wv);
            }
        } else if (tid == nPair) {
            float e = 0.f;
            for (unsigned r2 = 0; r2 < csz; ++r2)
                e += ld_dsmem_f32(mapa_u32(err_u32, r2));
            sBreak = (e < 1.28e-4f) ? 1 : 0;   // stricter than ref's global break
        }
        CLUSTER_SYNC();
        if (sBreak) break;
    }

    if (tid < rowsPerCta)
        g_a[b * NSEQ + (int)rank * rowsPerCta + tid] = sa[tid];
    if (tid < colsPerCta)
        g_w[b * NSEQ + (int)rank * colsPerCta + tid] = sw[(int)rank * colsPerCta + tid];
}

// ---------------- kernel 4: out = a (.) (S (w (.) V)) + V ----------------
// grid (64, 8): 16-row blocks x batch, 256 threads. Single resident wave.
// Thread = (r = tid&15 row, dg = tid>>4 d-group of 4). f32x2 inner loop.
__global__ void __launch_bounds__(256) out_kernel(const float* __restrict__ V,
                                                  float* __restrict__ out) {
    int b  = blockIdx.y;
    int i0 = blockIdx.x * 16;
    extern __shared__ __align__(16) float dynO[];
    float* Yt  = dynO;              // [128][64] fp32, 32 KB
    float* Ssm = dynO + 128*64;     // [16][132] fp32, 8.25 KB
    __shared__ float wt[128];

    int tid = threadIdx.x;
    int r   = tid & 15;     // row within 16-row block
    int dg  = tid >> 4;     // d-group: d = 4*dg .. +3

    ull acc01 = 0ull, acc23 = 0ull;

    const float* Vb = V + (size_t)b * NSEQ * DIM;

    for (int jt = 0; jt < NSEQ; jt += 128) {
        __syncthreads();
        if (tid < 128) wt[tid] = g_w[b * NSEQ + jt + tid];
        __syncthreads();
        // Yt[j][d] = w[jt+j] * V[b][jt+j][d]   (2048 float4 / 256 threads = 8 each)
        #pragma unroll
        for (int t0 = 0; t0 < 8; ++t0) {
            int t = tid + t0 * 256;
            int j = t >> 4, dq = t & 15;
            float4 v4 = reinterpret_cast<const float4*>(Vb + (size_t)(jt + j) * DIM)[dq];
            float wv = wt[j];
            *reinterpret_cast<float4*>(&Yt[j*64 + dq*4]) =
                make_float4(v4.x*wv, v4.y*wv, v4.z*wv, v4.w*wv);
        }
        // Ssm[r2][j] = S[b][i0+r2][jt+j] fp32   (16 rows x 128 cols, one uint4/thread)
        {
            const __nv_bfloat16* Sb2 = g_S + ((size_t)(b * NSEQ + i0) << 10) + jt;
            int r2 = tid >> 4, jq = tid & 15;
            uint4 v = *reinterpret_cast<const uint4*>(Sb2 + ((size_t)r2 << 10) + jq*8);
            float* dst = &Ssm[r2*132 + jq*8];
            *reinterpret_cast<float4*>(dst)     = make_float4(bflo(v.x), bfhi(v.x), bflo(v.y), bfhi(v.y));
            *reinterpret_cast<float4*>(dst + 4) = make_float4(bflo(v.z), bfhi(v.z), bflo(v.w), bfhi(v.w));
        }
        __syncthreads();

        const float* srow  = &Ssm[r * 132];
        const float* ybase = &Yt[dg * 4];
        #pragma unroll 8
        for (int j2 = 0; j2 < 64; ++j2) {
            ull spair = *reinterpret_cast<const ull*>(srow + j2*2);
            float s0, s1; unpack2(spair, s0, s1);
            ull s00 = dup2(s0);
            ull s11 = dup2(s1);
            ulonglong2 ya = *reinterpret_cast<const ulonglong2*>(ybase + (2*j2    )*64);
            ulonglong2 yb = *reinterpret_cast<const ulonglong2*>(ybase + (2*j2 + 1)*64);
            acc01 = fma2(s00, ya.x, acc01);
            acc23 = fma2(s00, ya.y, acc23);
            acc01 = fma2(s11, yb.x, acc01);
            acc23 = fma2(s11, yb.y, acc23);
        }
    }

    int row = i0 + r;
    float a = g_a[b * NSEQ + row];
    float a0, a1, a2, a3;
    unpack2(acc01, a0, a1);
    unpack2(acc23, a2, a3);
    float4 v4 = *reinterpret_cast<const float4*>(&Vb[(size_t)row * DIM + dg*4]);
    float4 o;
    o.x = fmaf(a0, a, v4.x);
    o.y = fmaf(a1, a, v4.y);
    o.z = fmaf(a2, a, v4.z);
    o.w = fmaf(a3, a, v4.w);
    *reinterpret_cast<float4*>(&out[((size_t)b * NSEQ + row) * DIM + dg*4]) = o;
}

// ---------------- launcher ----------------
extern "C" void kernel_launch(void* const* d_in, const int* in_sizes, int n_in,
                              void* d_out, int out_size) {
    const float* q = (const float*)d_in[0];
    const float* k = (const float*)d_in[1];
    const float* V = (const float*)d_in[2];
    float* out = (float*)d_out;
    (void)in_sizes; (void)n_in; (void)out_size;

    const int outSmem  = (128*64 + 16*132) * (int)sizeof(float);        // 41216
    const int sinkSmem = 18432 * (int)sizeof(float) + 72 * 2048;        // 73728 + 147456 = 221184

    cudaFuncSetAttribute(out_kernel,  cudaFuncAttributeMaxDynamicSharedMemorySize, outSmem);
    cudaFuncSetAttribute(sink_kernel, cudaFuncAttributeMaxDynamicSharedMemorySize, sinkSmem);
    cudaFuncSetAttribute(sink_kernel, cudaFuncAttributeNonPortableClusterSizeAllowed, 1);

    int csz = 8;
    {
        int maxC = 0;
        cudaLaunchConfig_t qcfg = {};
        qcfg.gridDim  = dim3(128);
        qcfg.blockDim = dim3(512);
        qcfg.dynamicSmemBytes = sinkSmem;
        if (cudaOccupancyMaxPotentialClusterSize(&maxC, sink_kernel, &qcfg) == cudaSuccess) {
            if (maxC >= 16) csz = 16;
        }
    }

    norm_kernel<<<2048, 256>>>(q, k);
    gemmS_kernel<<<dim3(32, 8), 256>>>();

    {
        cudaLaunchAttribute at;
        at.id = cudaLaunchAttributeClusterDimension;
        at.val.clusterDim.x = (unsigned)csz;
        at.val.clusterDim.y = 1;
        at.val.clusterDim.z = 1;
        cudaLaunchConfig_t cfg = {};
        cfg.gridDim  = dim3((unsigned)(BATCH * csz));
        cfg.blockDim = dim3(512);
        cfg.dynamicSmemBytes = sinkSmem;
        cfg.stream = 0;
        cfg.attrs = &at;
        cfg.numAttrs = 1;
        cudaLaunchKernelEx(&cfg, sink_kernel);
    }

    out_kernel<<<dim3(64, 8), 256, outSmem>>>(V, out);
}

// round 17
// speedup vs baseline: 1.5825x; 1.0277x over previous
#include <cuda_runtime.h>
#include <cuda_bf16.h>

// ---------------------------------------------------------------------------
// OT (Sinkhorn) attention, B=8, N=1024, D=64, fp32.
// Scaling-form Sinkhorn, fused row pass in packed f32x2 (FFMA2), SMEM-resident
// S slice, single-stage column reduce, b64 cluster exchange.
// ---------------------------------------------------------------------------

#define BATCH 8
#define NSEQ  1024
#define DIM   64
#define EPS_F 0.05f
#define MU_F  (1.0f/1024.0f + 1e-8f)

typedef unsigned long long ull;

__device__ __nv_bfloat16 g_S[(size_t)BATCH * NSEQ * NSEQ];   // 16 MB
__device__ float g_Qn[BATCH * NSEQ * DIM];
__device__ float g_Kn[BATCH * NSEQ * DIM];
__device__ float g_a[BATCH * NSEQ];
__device__ float g_w[BATCH * NSEQ];

// ---------------- helpers ----------------
__device__ __forceinline__ float bflo(unsigned x) { return __uint_as_float(x << 16); }
__device__ __forceinline__ float bfhi(unsigned x) { return __uint_as_float(x & 0xFFFF0000u); }

__device__ __forceinline__ unsigned pk2(float a, float b) {
    __nv_bfloat162 t = __floats2bfloat162_rn(a, b);  // .x = a (low)
    return *reinterpret_cast<unsigned*>(&t);
}

// ---- packed f32x2 ----
__device__ __forceinline__ ull fma2(ull a, ull b, ull c) {
    ull d; asm("fma.rn.f32x2 %0, %1, %2, %3;" : "=l"(d) : "l"(a), "l"(b), "l"(c)); return d;
}
__device__ __forceinline__ ull add2(ull a, ull b) {
    ull d; asm("add.rn.f32x2 %0, %1, %2;" : "=l"(d) : "l"(a), "l"(b)); return d;
}
__device__ __forceinline__ ull pack2u(unsigned lo, unsigned hi) {
    ull r; asm("mov.b64 %0, {%1, %2};" : "=l"(r) : "r"(lo), "r"(hi)); return r;
}
__device__ __forceinline__ void unpack2(ull p, float& lo, float& hi) {
    unsigned a, b;
    asm("mov.b64 {%0, %1}, %2;" : "=r"(a), "=r"(b) : "l"(p));
    lo = __uint_as_float(a); hi = __uint_as_float(b);
}
__device__ __forceinline__ ull dup2(float s) {
    unsigned u = __float_as_uint(s);
    return pack2u(u, u);
}
// bf16 pair (u32) -> packed f32x2 {lo, hi}
__device__ __forceinline__ ull bf2pack(unsigned x) {
    return pack2u(x << 16, x & 0xFFFF0000u);
}

__device__ __forceinline__ unsigned smem_u32(const void* p) {
    unsigned a;
    asm("{ .reg .u64 t; cvta.to.shared.u64 t, %1; cvt.u32.u64 %0, t; }" : "=r"(a) : "l"(p));
    return a;
}
__device__ __forceinline__ unsigned cluster_rank() {
    unsigned r; asm("mov.u32 %0, %%cluster_ctarank;" : "=r"(r)); return r;
}
__device__ __forceinline__ unsigned cluster_nctas() {
    unsigned r; asm("mov.u32 %0, %%cluster_nctaid.x;" : "=r"(r)); return r;
}
__device__ __forceinline__ unsigned mapa_u32(unsigned addr, unsigned rank) {
    unsigned r; asm("mapa.shared::cluster.u32 %0, %1, %2;" : "=r"(r) : "r"(addr), "r"(rank));
    return r;
}
__device__ __forceinline__ float ld_dsmem_f32(unsigned addr) {
    float v; asm volatile("ld.shared::cluster.f32 %0, [%1];" : "=f"(v) : "r"(addr)); return v;
}
__device__ __forceinline__ ull ld_dsmem_b64(unsigned addr) {
    ull v; asm volatile("ld.shared::cluster.b64 %0, [%1];" : "=l"(v) : "r"(addr)); return v;
}
__device__ __forceinline__ void st_dsmem_b64(unsigned addr, ull v) {
    asm volatile("st.shared::cluster.b64 [%0], %1;" :: "r"(addr), "l"(v));
}
#define CLUSTER_SYNC() do { \
    asm volatile("barrier.cluster.arrive.aligned;" ::: "memory"); \
    asm volatile("barrier.cluster.wait.aligned;"   ::: "memory"); \
} while (0)

// ---------------- kernel 1: L2-normalize rows of q,k ----------------
__global__ void __launch_bounds__(256) norm_kernel(const float* __restrict__ q,
                                                   const float* __restrict__ k) {
    int gw   = (blockIdx.x * 256 + threadIdx.x) >> 5;
    int lane = threadIdx.x & 31;
    const float* src;
    float* dst;
    if (gw < BATCH * NSEQ) { src = q + (size_t)gw * DIM;                dst = g_Qn + (size_t)gw * DIM; }
    else                   { src = k + (size_t)(gw - BATCH*NSEQ) * DIM; dst = g_Kn + (size_t)(gw - BATCH*NSEQ) * DIM; }
    float2 v = reinterpret_cast<const float2*>(src)[lane];
    float s = v.x * v.x + v.y * v.y;
    #pragma unroll
    for (int o = 16; o > 0; o >>= 1) s += __shfl_xor_sync(~0u, s, o);
    float n   = sqrtf(s);
    float inv = 1.0f / fmaxf(n, 1e-12f);
    reinterpret_cast<float2*>(dst)[lane] = make_float2(v.x * inv, v.y * inv);
}

// ---------------- kernel 2: S = exp((QK^T - 1)/eps), bf16; f32x2 packed ----------------
__global__ void __launch_bounds__(256) gemmS_kernel() {
    int b  = blockIdx.y;
    int i0 = blockIdx.x * 32;
    __shared__ __align__(16) float Qs[32][DIM];
    __shared__ __align__(16) float Ks[128][DIM];

    const float* Qp = g_Qn + (size_t)(b * NSEQ + i0) * DIM;
    for (int t = threadIdx.x; t < 32 * DIM / 4; t += 256)
        reinterpret_cast<float4*>(&Qs[0][0])[t] = reinterpret_cast<const float4*>(Qp)[t];

    int ti = threadIdx.x >> 5;
    int tj = threadIdx.x & 31;

    for (int jt = 0; jt < NSEQ; jt += 128) {
        __syncthreads();
        const float* Kp = g_Kn + (size_t)(b * NSEQ + jt) * DIM;
        for (int t = threadIdx.x; t < 128 * DIM / 4; t += 256)
            reinterpret_cast<float4*>(&Ks[0][0])[t] = reinterpret_cast<const float4*>(Kp)[t];
        __syncthreads();

        ull accp[4][4];
        #pragma unroll
        for (int r = 0; r < 4; ++r)
            #pragma unroll
            for (int c = 0; c < 4; ++c) accp[r][c] = 0ull;

        #pragma unroll
        for (int d = 0; d < DIM; d += 4) {
            ulonglong2 qp[4], kp[4];
            #pragma unroll
            for (int r = 0; r < 4; ++r) qp[r] = *reinterpret_cast<const ulonglong2*>(&Qs[4*ti + r][d]);
            #pragma unroll
            for (int c = 0; c < 4; ++c) kp[c] = *reinterpret_cast<const ulonglong2*>(&Ks[4*tj + c][d]);
            #pragma unroll
            for (int r = 0; r < 4; ++r)
                #pragma unroll
                for (int c = 0; c < 4; ++c) {
                    accp[r][c] = fma2(qp[r].x, kp[c].x, accp[r][c]);
                    accp[r][c] = fma2(qp[r].y, kp[c].y, accp[r][c]);
                }
        }

        #pragma unroll
        for (int r = 0; r < 4; ++r) {
            size_t rowi = (size_t)(b * NSEQ + i0 + 4*ti + r);
            float e[4];
            #pragma unroll
            for (int c = 0; c < 4; ++c) {
                float lo, hi; unpack2(accp[r][c], lo, hi);
                e[c] = __expf(20.0f * ((lo + hi) - 1.0f));
            }
            uint2 p = make_uint2(pk2(e[0], e[1]), pk2(e[2], e[3]));
            *reinterpret_cast<uint2*>(g_S + (rowi << 10) + jt + 4*tj) = p;
        }
    }
}

// ---------------- kernel 3: fused Sinkhorn loop, packed FFMA2 row pass ----------------
// grid = BATCH * csz CTAs, cluster per batch, 512 threads.
// dyn smem (floats): sw[1024] | spc[1024] | wbuf[16][1024] | Ssm (<=72 rows x 2KB)
__global__ void __launch_bounds__(512) sink_kernel() {
    extern __shared__ __align__(16) float dynS[];
    float* sw   = dynS;                  // 4 KB
    float* spc  = dynS + 1024;           // 4 KB
    float* wbuf = dynS + 2048;           // 64 KB: [16][1024]
    uint4* SsmV = reinterpret_cast<uint4*>(dynS + 18432);  // up to 144 KB

    __shared__ float sa[128];
    __shared__ float swErr[16];
    __shared__ float sErrTot;
    __shared__ int   sBreak;

    unsigned csz  = cluster_nctas();          // 8 or 16
    unsigned rank = cluster_rank();
    int b           = blockIdx.x / (int)csz;
    int rowsPerCta  = NSEQ / (int)csz;        // 128 or 64
    int rowsPerWarp = rowsPerCta >> 4;        // 8 or 4
    int colsPerCta  = NSEQ / (int)csz;
    int rowsInS     = (csz == 16) ? 64 : 72;  // smem-resident rows
    int tid  = threadIdx.x;
    int wid  = tid >> 5;
    int lane = tid & 31;

    for (int t = tid; t < NSEQ; t += 512) sw[t] = 1.0f;
    if (tid < rowsPerCta) sa[tid] = 1.0f;
    if (tid == 0) sBreak = 0;

    const __nv_bfloat16* Sbase = g_S + ((size_t)(b * NSEQ + (int)rank * rowsPerCta) << 10);

    // preload S rows [0, rowsInS) into shared memory
    {
        const uint4* src = reinterpret_cast<const uint4*>(Sbase);
        int nvec = rowsInS * 128;
        for (int t = tid; t < nvec; t += 512) SsmV[t] = src[t];
    }
    __syncthreads();

    unsigned spc_u32 = smem_u32(spc);
    unsigned sw_u32  = smem_u32(sw);
    unsigned err_u32 = smem_u32(&sErrTot);

    #pragma unroll 1
    for (int iter = 0; iter < 100; ++iter) {
        // preload w packed pairs: wp[c][p] = {w[c*256+lane*8+2p], w[..+2p+1]}
        ull wp[4][4];
        #pragma unroll
        for (int c = 0; c < 4; ++c) {
            ulonglong2 w0 = *reinterpret_cast<const ulonglong2*>(&sw[c*256 + lane*8]);
            ulonglong2 w1 = *reinterpret_cast<const ulonglong2*>(&sw[c*256 + lane*8 + 4]);
            wp[c][0] = w0.x; wp[c][1] = w0.y; wp[c][2] = w1.x; wp[c][3] = w1.y;
        }

        ull cc[4][4];
        #pragma unroll
        for (int c = 0; c < 4; ++c)
            #pragma unroll
            for (int p = 0; p < 4; ++p) cc[c][p] = 0ull;

        float errAcc = 0.f;

        // per row: packed dot -> a_new -> packed rank-1 (s pairs kept in regs)
        auto process = [&](const uint4 (&v)[4], int row) {
            ull s[16];
            #pragma unroll
            for (int c = 0; c < 4; ++c) {
                s[c*4+0] = bf2pack(v[c].x);
                s[c*4+1] = bf2pack(v[c].y);
                s[c*4+2] = bf2pack(v[c].z);
                s[c*4+3] = bf2pack(v[c].w);
            }
            ull d0 = 0ull, d1 = 0ull, d2 = 0ull, d3 = 0ull;
            #pragma unroll
            for (int c = 0; c < 4; ++c) {
                d0 = fma2(s[c*4+0], wp[c][0], d0);
                d1 = fma2(s[c*4+1], wp[c][1], d1);
                d2 = fma2(s[c*4+2], wp[c][2], d2);
                d3 = fma2(s[c*4+3], wp[c][3], d3);
            }
            ull dt = add2(add2(d0, d1), add2(d2, d3));
            float lo, hi; unpack2(dt, lo, hi);
            float acc = lo + hi;
            #pragma unroll
            for (int o = 16; o > 0; o >>= 1) acc += __shfl_xor_sync(~0u, acc, o);
            float anew = MU_F / acc;
            if (lane == 0) {
                float aold = sa[row];
                sa[row] = anew;
                errAcc += fabsf(EPS_F * (__logf(anew) - __logf(aold)));
            }
            ull an2 = dup2(anew);
            #pragma unroll
            for (int c = 0; c < 4; ++c) {
                cc[c][0] = fma2(s[c*4+0], an2, cc[c][0]);
                cc[c][1] = fma2(s[c*4+1], an2, cc[c][1]);
                cc[c][2] = fma2(s[c*4+2], an2, cc[c][2]);
                cc[c][3] = fma2(s[c*4+3], an2, cc[c][3]);
            }
        };

        int row0 = wid * rowsPerWarp;
        if (row0 + rowsPerWarp <= rowsInS) {
            #pragma unroll 1
            for (int r8 = 0; r8 < rowsPerWarp; ++r8) {
                int row = row0 + r8;
                const uint4* p = SsmV + row * 128;
                uint4 v[4];
                #pragma unroll
                for (int c = 0; c < 4; ++c) v[c] = p[c*32 + lane];
                process(v, row);
            }
        } else {
            #pragma unroll 1
            for (int r8 = 0; r8 < rowsPerWarp; ++r8) {
                int row = row0 + r8;
                const uint4* p = reinterpret_cast<const uint4*>(Sbase + ((size_t)row << 10));
                uint4 v[4];
                #pragma unroll
                for (int c = 0; c < 4; ++c) v[c] = p[c*32 + lane];
                process(v, row);
            }
        }
        if (lane == 0) swErr[wid] = errAcc;

        // ---- store warp partials to wbuf (packed pairs = contiguous floats)
        #pragma unroll
        for (int c = 0; c < 4; ++c) {
            float* dst = &wbuf[wid*1024 + c*256 + lane*8];
            ulonglong2 t0; t0.x = cc[c][0]; t0.y = cc[c][1];
            ulonglong2 t1; t1.x = cc[c][2]; t1.y = cc[c][3];
            *reinterpret_cast<ulonglong2*>(dst)     = t0;
            *reinterpret_cast<ulonglong2*>(dst + 4) = t1;
        }
        __syncthreads();

        // ---- single-stage reduce: each thread sums a column PAIR over 16 warps
        {
            int col0 = tid * 2;
            ull s = 0ull;
            #pragma unroll
            for (int wu = 0; wu < 16; ++wu) {
                ull x = *reinterpret_cast<const ull*>(&wbuf[wu*1024 + col0]);
                s = add2(s, x);
            }
            *reinterpret_cast<ull*>(&spc[col0]) = s;
        }
        if (tid == 0) {
            float e = 0.f;
            #pragma unroll
            for (int t2 = 0; t2 < 16; ++t2) e += swErr[t2];
            sErrTot = e;
        }
        CLUSTER_SYNC();   // spc / sErrTot visible cluster-wide

        // ---- cross-CTA: rank owns colsPerCta cols; b64 pair exchange
        int nPair = colsPerCta >> 1;
        if (tid < nPair) {
            int col2 = (int)rank * colsPerCta + tid * 2;
            unsigned off = 4u * (unsigned)col2;
            ull cs = 0ull;
            if (csz == 16) {
                #pragma unroll
                for (unsigned r2 = 0; r2 < 16; ++r2)
                    cs = add2(cs, ld_dsmem_b64(mapa_u32(spc_u32 + off, r2)));
            } else {
                for (unsigned r2 = 0; r2 < csz; ++r2)
                    cs = add2(cs, ld_dsmem_b64(mapa_u32(spc_u32 + off, r2)));
            }
            float c0, c1; unpack2(cs, c0, c1);
            float w0 = MU_F / c0;
            float w1 = MU_F / c1;
            ull wv = pack2u(__float_as_uint(w0), __float_as_uint(w1));
            if (csz == 16) {
                #pragma unroll
                for (unsigned r2 = 0; r2 < 16; ++r2)
                    st_dsmem_b64(mapa_u32(sw_u32 + off, r2), wv);
            } else {
                for (unsigned r2 = 0; r2 < csz; ++r2)
                    st_dsmem_b64(mapa_u32(sw_u32 + off, r2), wv);
            }
        } else if (tid == nPair) {
            float e = 0.f;
            for (unsigned r2 = 0; r2 < csz; ++r2)
                e += ld_dsmem_f32(mapa_u32(err_u32, r2));
            sBreak = (e < 1.28e-4f) ? 1 : 0;   // stricter than ref's global break
        }
        CLUSTER_SYNC();
        if (sBreak) break;
    }

    if (tid < rowsPerCta)
        g_a[b * NSEQ + (int)rank * rowsPerCta + tid] = sa[tid];
    if (tid < colsPerCta)
        g_w[b * NSEQ + (int)rank * colsPerCta + tid] = sw[(int)rank * colsPerCta + tid];
}

// ---------------- kernel 4: out = a (.) (S (w (.) V)) + V  (R9 proven version) ----------------
// grid (32, 8): 32-row blocks x batch, 512 threads (16 warps), 2 CTAs/SM.
__global__ void __launch_bounds__(512) out_kernel(const float* __restrict__ V,
                                                  float* __restrict__ out) {
    int b  = blockIdx.y;
    int i0 = blockIdx.x * 32;
    extern __shared__ float dynO[];
    float* Yt  = dynO;              // [128][64] fp32, 32 KB
    float* Ssm = dynO + 128*64;     // [32][132] fp32, 16.5 KB
    __shared__ float wt[128];

    int tid  = threadIdx.x;
    int wid  = tid >> 5;    // d-group: d = 4*wid .. +3
    int lane = tid & 31;    // row within 32-row block

    float acc0 = 0.f, acc1 = 0.f, acc2 = 0.f, acc3 = 0.f;

    const float* Vb = V + (size_t)b * NSEQ * DIM;

    for (int jt = 0; jt < NSEQ; jt += 128) {
        __syncthreads();
        if (tid < 128) wt[tid] = g_w[b * NSEQ + jt + tid];
        __syncthreads();
        #pragma unroll
        for (int t0 = 0; t0 < 4; ++t0) {
            int t = tid + t0 * 512;
            int j = t >> 4, dq = t & 15;
            float4 v4 = reinterpret_cast<const float4*>(Vb + (size_t)(jt + j) * DIM)[dq];
            float wv = wt[j];
            *reinterpret_cast<float4*>(&Yt[j*64 + dq*4]) =
                make_float4(v4.x*wv, v4.y*wv, v4.z*wv, v4.w*wv);
        }
        {
            const __nv_bfloat16* Sb2 = g_S + ((size_t)(b * NSEQ + i0) << 10) + jt;
            int r = tid >> 4, jq = tid & 15;
            uint4 v = *reinterpret_cast<const uint4*>(Sb2 + ((size_t)r << 10) + jq*8);
            float* dst = &Ssm[r*132 + jq*8];
            *reinterpret_cast<float4*>(dst)     = make_float4(bflo(v.x), bfhi(v.x), bflo(v.y), bfhi(v.y));
            *reinterpret_cast<float4*>(dst + 4) = make_float4(bflo(v.z), bfhi(v.z), bflo(v.w), bfhi(v.w));
        }
        __syncthreads();

        const float* srow = &Ssm[lane * 132];
        const float* ybase = &Yt[wid * 4];
        #pragma unroll 4
        for (int j4 = 0; j4 < 32; ++j4) {
            float4 s4 = *reinterpret_cast<const float4*>(srow + j4*4);
            float4 ya = *reinterpret_cast<const float4*>(ybase + (j4*4 + 0)*64);
            float4 yb = *reinterpret_cast<const float4*>(ybase + (j4*4 + 1)*64);
            float4 yc = *reinterpret_cast<const float4*>(ybase + (j4*4 + 2)*64);
            float4 yd = *reinterpret_cast<const float4*>(ybase + (j4*4 + 3)*64);
            acc0 = fmaf(s4.x, ya.x, acc0); acc1 = fmaf(s4.x, ya.y, acc1);
            acc2 = fmaf(s4.x, ya.z, acc2); acc3 = fmaf(s4.x, ya.w, acc3);
            acc0 = fmaf(s4.y, yb.x, acc0); acc1 = fmaf(s4.y, yb.y, acc1);
            acc2 = fmaf(s4.y, yb.z, acc2); acc3 = fmaf(s4.y, yb.w, acc3);
            acc0 = fmaf(s4.z, yc.x, acc0); acc1 = fmaf(s4.z, yc.y, acc1);
            acc2 = fmaf(s4.z, yc.z, acc2); acc3 = fmaf(s4.z, yc.w, acc3);
            acc0 = fmaf(s4.w, yd.x, acc0); acc1 = fmaf(s4.w, yd.y, acc1);
            acc2 = fmaf(s4.w, yd.z, acc2); acc3 = fmaf(s4.w, yd.w, acc3);
        }
    }

    int row = i0 + lane;
    float a = g_a[b * NSEQ + row];
    float4 v4 = *reinterpret_cast<const float4*>(&Vb[(size_t)row * DIM + wid*4]);
    float4 o;
    o.x = fmaf(acc0, a, v4.x);
    o.y = fmaf(acc1, a, v4.y);
    o.z = fmaf(acc2, a, v4.z);
    o.w = fmaf(acc3, a, v4.w);
    *reinterpret_cast<float4*>(&out[((size_t)b * NSEQ + row) * DIM + wid*4]) = o;
}

// ---------------- launcher ----------------
extern "C" void kernel_launch(void* const* d_in, const int* in_sizes, int n_in,
                              void* d_out, int out_size) {
    const float* q = (const float*)d_in[0];
    const float* k = (const float*)d_in[1];
    const float* V = (const float*)d_in[2];
    float* out = (float*)d_out;
    (void)in_sizes; (void)n_in; (void)out_size;

    const int outSmem  = (128*64 + 32*132) * (int)sizeof(float);        // 49664
    const int sinkSmem = 18432 * (int)sizeof(float) + 72 * 2048;        // 221184

    cudaFuncSetAttribute(out_kernel,  cudaFuncAttributeMaxDynamicSharedMemorySize, outSmem);
    cudaFuncSetAttribute(sink_kernel, cudaFuncAttributeMaxDynamicSharedMemorySize, sinkSmem);
    cudaFuncSetAttribute(sink_kernel, cudaFuncAttributeNonPortableClusterSizeAllowed, 1);

    int csz = 8;
    {
        int maxC = 0;
        cudaLaunchConfig_t qcfg = {};
        qcfg.gridDim  = dim3(128);
        qcfg.blockDim = dim3(512);
        qcfg.dynamicSmemBytes = sinkSmem;
        if (cudaOccupancyMaxPotentialClusterSize(&maxC, sink_kernel, &qcfg) == cudaSuccess) {
            if (maxC >= 16) csz = 16;
        }
    }

    norm_kernel<<<2048, 256>>>(q, k);
    gemmS_kernel<<<dim3(32, 8), 256>>>();

    {
        cudaLaunchAttribute at;
        at.id = cudaLaunchAttributeClusterDimension;
        at.val.clusterDim.x = (unsigned)csz;
        at.val.clusterDim.y = 1;
        at.val.clusterDim.z = 1;
        cudaLaunchConfig_t cfg = {};
        cfg.gridDim  = dim3((unsigned)(BATCH * csz));
        cfg.blockDim = dim3(512);
        cfg.dynamicSmemBytes = sinkSmem;
        cfg.stream = 0;
        cfg.attrs = &at;
        cfg.numAttrs = 1;
        cudaLaunchKernelEx(&cfg, sink_kernel);
    }

    out_kernel<<<dim3(32, 8), 512, outSmem>>>(V, out);
}